// round 4
// baseline (speedup 1.0000x reference)
#include <cuda_runtime.h>

// ---------------------------------------------------------------------------
// Multi-slice ptychography, fused, f32x2-packed, 3-shuffle-stage FFT.
// One CTA = one (mode,k). Wave in SMEM (pitch 129). Each 8-lane group owns
// one f32x2-packed line pair with 16 values per lane (idx = l8 + 8*j).
// FFT128: spans 64/32/16/8 register-local, spans 4/2/1 via shfl_xor.
// Crossbar (shfl) traffic cut 40% vs the 5-stage layout.
// ---------------------------------------------------------------------------

typedef unsigned long long u64;

#define PITCH 129
#define SMEM_FLOATS (2 * 128 * PITCH)

static __device__ float g_int[4u * 256u * 128u * 128u];   // 64 MB scratch

// ----------------------------- f32x2 helpers --------------------------------
__device__ __forceinline__ u64 pk(float a, float b) {
    u64 r; asm("mov.b64 %0,{%1,%2};" : "=l"(r) : "f"(a), "f"(b)); return r;
}
__device__ __forceinline__ void upk(u64 v, float& a, float& b) {
    asm("mov.b64 {%0,%1},%2;" : "=f"(a), "=f"(b) : "l"(v));
}
__device__ __forceinline__ u64 f2add(u64 a, u64 b) {
    u64 d; asm("add.rn.f32x2 %0,%1,%2;" : "=l"(d) : "l"(a), "l"(b)); return d;
}
__device__ __forceinline__ u64 f2sub(u64 a, u64 b) {
    u64 d; asm("sub.rn.f32x2 %0,%1,%2;" : "=l"(d) : "l"(a), "l"(b)); return d;
}
__device__ __forceinline__ u64 f2mul(u64 a, u64 b) {
    u64 d; asm("mul.rn.f32x2 %0,%1,%2;" : "=l"(d) : "l"(a), "l"(b)); return d;
}
__device__ __forceinline__ u64 f2fma(u64 a, u64 b, u64 c) {
    u64 d; asm("fma.rn.f32x2 %0,%1,%2,%3;" : "=l"(d) : "l"(a), "l"(b), "l"(c)); return d;
}
__device__ __forceinline__ u64 shx(u64 v, int s) {
    float a, b; upk(v, a, b);
    a = __shfl_xor_sync(0xffffffffu, a, s);
    b = __shfl_xor_sync(0xffffffffu, b, s);
    return pk(a, b);
}

// forward complex mult by scalar twiddle (tr, ti), broadcast to both halves
__device__ __forceinline__ void cmul_sc(u64& r, u64& i, float tr, float ti) {
    u64 Tr = pk(tr, tr), Ti = pk(ti, ti);
    u64 rr = f2sub(f2mul(r, Tr), f2mul(i, Ti));
    i = f2fma(r, Ti, f2mul(i, Tr));
    r = rr;
}
// conjugate complex mult by scalar twiddle (tr, ti)
__device__ __forceinline__ void cmulc_sc(u64& r, u64& i, float tr, float ti) {
    u64 Tr = pk(tr, tr), Ti = pk(ti, ti);
    u64 rr = f2fma(i, Ti, f2mul(r, Tr));
    i = f2sub(f2mul(i, Tr), f2mul(r, Ti));
    r = rr;
}

// ------------------------- twiddle context ----------------------------------
// W_e = exp(-2*pi*i*e/128), stored (c, -s). Per lane l8 = lane & 7.
struct Tw3 {
    float w64r[8], w64i[8];   // e = l8 + 8j,      j=0..7   (span 64)
    float w32r[4], w32i[4];   // e = 2(l8 + 8j),   j=0..3   (span 32)
    float w16r[2], w16i[2];   // e = 4(l8 + 8j),   j=0..1   (span 16)
    float w8r, w8i;           // e = 8*l8                    (span 8)
    u64 c4r, c4i, n4i;        // effective span-4 cross twiddle (hi lanes)
    u64 c2r, c2i, n2i;        // effective span-2 cross twiddle
    u64 sg4, sg2, sg1;        // butterfly signs
};

__device__ __forceinline__ void dif16(u64 (&R)[16], u64 (&I)[16], const Tw3& T)
{
    // span 64: pairs (j, j+8)
#pragma unroll
    for (int j = 0; j < 8; j++) {
        u64 dr = f2sub(R[j], R[j + 8]), di = f2sub(I[j], I[j + 8]);
        R[j] = f2add(R[j], R[j + 8]);  I[j] = f2add(I[j], I[j + 8]);
        R[j + 8] = dr;  I[j + 8] = di;
        cmul_sc(R[j + 8], I[j + 8], T.w64r[j], T.w64i[j]);
    }
    // span 32: pairs (j, j+4) within halves
#pragma unroll
    for (int b = 0; b < 16; b += 8)
#pragma unroll
        for (int j2 = 0; j2 < 4; j2++) {
            int j = b + j2;
            u64 dr = f2sub(R[j], R[j + 4]), di = f2sub(I[j], I[j + 4]);
            R[j] = f2add(R[j], R[j + 4]);  I[j] = f2add(I[j], I[j + 4]);
            R[j + 4] = dr;  I[j + 4] = di;
            cmul_sc(R[j + 4], I[j + 4], T.w32r[j2], T.w32i[j2]);
        }
    // span 16: pairs (j, j+2)
#pragma unroll
    for (int b = 0; b < 16; b += 4)
#pragma unroll
        for (int j2 = 0; j2 < 2; j2++) {
            int j = b + j2;
            u64 dr = f2sub(R[j], R[j + 2]), di = f2sub(I[j], I[j + 2]);
            R[j] = f2add(R[j], R[j + 2]);  I[j] = f2add(I[j], I[j + 2]);
            R[j + 2] = dr;  I[j + 2] = di;
            cmul_sc(R[j + 2], I[j + 2], T.w16r[j2], T.w16i[j2]);
        }
    // span 8: pairs (j, j+1)
#pragma unroll
    for (int b = 0; b < 16; b += 2) {
        u64 dr = f2sub(R[b], R[b + 1]), di = f2sub(I[b], I[b + 1]);
        R[b] = f2add(R[b], R[b + 1]);  I[b] = f2add(I[b], I[b + 1]);
        R[b + 1] = dr;  I[b + 1] = di;
        cmul_sc(R[b + 1], I[b + 1], T.w8r, T.w8i);
    }
    // cross span 4
#pragma unroll
    for (int j = 0; j < 16; j++) {
        u64 pR = shx(R[j], 4), pI = shx(I[j], 4);
        u64 xR = f2fma(T.sg4, R[j], pR);
        u64 xI = f2fma(T.sg4, I[j], pI);
        R[j] = f2fma(xI, T.n4i, f2mul(xR, T.c4r));
        I[j] = f2fma(xI, T.c4r, f2mul(xR, T.c4i));
    }
    // cross span 2
#pragma unroll
    for (int j = 0; j < 16; j++) {
        u64 pR = shx(R[j], 2), pI = shx(I[j], 2);
        u64 xR = f2fma(T.sg2, R[j], pR);
        u64 xI = f2fma(T.sg2, I[j], pI);
        R[j] = f2fma(xI, T.n2i, f2mul(xR, T.c2r));
        I[j] = f2fma(xI, T.c2r, f2mul(xR, T.c2i));
    }
    // cross span 1 (no twiddle)
#pragma unroll
    for (int j = 0; j < 16; j++) {
        u64 pR = shx(R[j], 1), pI = shx(I[j], 1);
        R[j] = f2fma(T.sg1, R[j], pR);
        I[j] = f2fma(T.sg1, I[j], pI);
    }
}

// Inverse (unnormalized), bit-reversed input -> natural output.
__device__ __forceinline__ void dit16(u64 (&R)[16], u64 (&I)[16], const Tw3& T)
{
    // cross span 1
#pragma unroll
    for (int j = 0; j < 16; j++) {
        u64 pR = shx(R[j], 1), pI = shx(I[j], 1);
        R[j] = f2fma(T.sg1, R[j], pR);
        I[j] = f2fma(T.sg1, I[j], pI);
    }
    // cross span 2 : conj effective twiddle, then exchange+combine
#pragma unroll
    for (int j = 0; j < 16; j++) {
        u64 uR = f2fma(I[j], T.c2i, f2mul(R[j], T.c2r));
        u64 uI = f2fma(R[j], T.n2i, f2mul(I[j], T.c2r));
        u64 pR = shx(uR, 2), pI = shx(uI, 2);
        R[j] = f2fma(T.sg2, uR, pR);
        I[j] = f2fma(T.sg2, uI, pI);
    }
    // cross span 4
#pragma unroll
    for (int j = 0; j < 16; j++) {
        u64 uR = f2fma(I[j], T.c4i, f2mul(R[j], T.c4r));
        u64 uI = f2fma(R[j], T.n4i, f2mul(I[j], T.c4r));
        u64 pR = shx(uR, 4), pI = shx(uI, 4);
        R[j] = f2fma(T.sg4, uR, pR);
        I[j] = f2fma(T.sg4, uI, pI);
    }
    // span 8: conj twiddle on b, then add/sub
#pragma unroll
    for (int b = 0; b < 16; b += 2) {
        u64 br = R[b + 1], bi = I[b + 1];
        cmulc_sc(br, bi, T.w8r, T.w8i);
        R[b + 1] = f2sub(R[b], br);  I[b + 1] = f2sub(I[b], bi);
        R[b] = f2add(R[b], br);      I[b] = f2add(I[b], bi);
    }
    // span 16
#pragma unroll
    for (int b = 0; b < 16; b += 4)
#pragma unroll
        for (int j2 = 0; j2 < 2; j2++) {
            int j = b + j2;
            u64 br = R[j + 2], bi = I[j + 2];
            cmulc_sc(br, bi, T.w16r[j2], T.w16i[j2]);
            R[j + 2] = f2sub(R[j], br);  I[j + 2] = f2sub(I[j], bi);
            R[j] = f2add(R[j], br);      I[j] = f2add(I[j], bi);
        }
    // span 32
#pragma unroll
    for (int b = 0; b < 16; b += 8)
#pragma unroll
        for (int j2 = 0; j2 < 4; j2++) {
            int j = b + j2;
            u64 br = R[j + 4], bi = I[j + 4];
            cmulc_sc(br, bi, T.w32r[j2], T.w32i[j2]);
            R[j + 4] = f2sub(R[j], br);  I[j + 4] = f2sub(I[j], bi);
            R[j] = f2add(R[j], br);      I[j] = f2add(I[j], bi);
        }
    // span 64
#pragma unroll
    for (int j = 0; j < 8; j++) {
        u64 br = R[j + 8], bi = I[j + 8];
        cmulc_sc(br, bi, T.w64r[j], T.w64i[j]);
        R[j + 8] = f2sub(R[j], br);  I[j + 8] = f2sub(I[j], bi);
        R[j] = f2add(R[j], br);      I[j] = f2add(I[j], bi);
    }
}

// ------------------------------- main kernel --------------------------------
__global__ void __launch_bounds__(512, 1)
msp_main(const float* __restrict__ V,
         const float* __restrict__ pre,
         const float* __restrict__ pim,
         const int*   __restrict__ ipos)
{
    extern __shared__ float smem[];
    float* sRe = smem;
    float* sIm = smem + 128 * PITCH;

    const int bid = blockIdx.x;
    const int k   = bid & 255;
    const int m   = bid >> 8;

    int py, px;
    {
        bool i64 = (ipos[1] | ipos[3] | ipos[5] | ipos[7] |
                    ipos[9] | ipos[11] | ipos[13] | ipos[15]) == 0;
        if (i64) { py = ipos[4 * k];  px = ipos[4 * k + 2]; }
        else     { py = ipos[2 * k];  px = ipos[2 * k + 1]; }
    }

    const int tid = threadIdx.x;
    const int l   = tid & 31;
    const int w   = tid >> 5;      // 16 warps
    const int g   = l >> 3;        // 4 groups of 8 lanes
    const int l8  = l & 7;
    const int w3  = w & 3;
    const int wh  = w >> 2;
    // line-pair base; bank = l8 + 8g + 2*w3 + const  -> conflict-free
    const int lineA = 32 * wh + 8 * g + 2 * w3;
    const int lineB = lineA + 1;

    Tw3 T;
    {
#pragma unroll
        for (int j = 0; j < 8; j++) {
            float s, c; sincospif((float)(l8 + 8 * j) * (1.0f / 64.0f), &s, &c);
            T.w64r[j] = c;  T.w64i[j] = -s;
        }
#pragma unroll
        for (int j = 0; j < 4; j++) {
            float s, c; sincospif((float)(2 * (l8 + 8 * j)) * (1.0f / 64.0f), &s, &c);
            T.w32r[j] = c;  T.w32i[j] = -s;
        }
#pragma unroll
        for (int j = 0; j < 2; j++) {
            float s, c; sincospif((float)(4 * (l8 + 8 * j)) * (1.0f / 64.0f), &s, &c);
            T.w16r[j] = c;  T.w16i[j] = -s;
        }
        { float s, c; sincospif((float)(8 * l8) * (1.0f / 64.0f), &s, &c);
          T.w8r = c;  T.w8i = -s; }
        { float s, c; sincospif((float)(16 * (l8 & 3)) * (1.0f / 64.0f), &s, &c);
          float tr = (l & 4) ? c : 1.0f, ti = (l & 4) ? -s : 0.0f;
          T.c4r = pk(tr, tr);  T.c4i = pk(ti, ti);  T.n4i = pk(-ti, -ti); }
        { float s, c; sincospif((float)(32 * (l8 & 1)) * (1.0f / 64.0f), &s, &c);
          float tr = (l & 2) ? c : 1.0f, ti = (l & 2) ? -s : 0.0f;
          T.c2r = pk(tr, tr);  T.c2i = pk(ti, ti);  T.n2i = pk(-ti, -ti); }
        float s4 = (l & 4) ? -1.0f : 1.0f;  T.sg4 = pk(s4, s4);
        float s2 = (l & 2) ? -1.0f : 1.0f;  T.sg2 = pk(s2, s2);
        float s1 = (l & 1) ? -1.0f : 1.0f;  T.sg1 = pk(s1, s1);
    }

    // Fresnel factors at bit-reversed stored positions, 1/128 folded in
    float Hr[16], Hi[16];
#pragma unroll
    for (int j = 0; j < 16; j++) {
        int idx = l8 + 8 * j;
        int fb  = (int)(__brev((unsigned)idx) >> 25);
        float f = (float)(fb < 64 ? fb : fb - 128) * (1.0f / 25.6f);
        float s, c;
        sincospif(-0.25f * f * f, &s, &c);      // lambda*dz = 0.25
        Hr[j] = c * (1.0f / 128.0f);
        Hi[j] = s * (1.0f / 128.0f);
    }

    const float* Vb   = V + (py * 512 + px);
    const float* prm  = pre + m * 16384;
    const float* pimm = pim + m * 16384;

#pragma unroll 1
    for (int pass = 0; pass < 16; pass++) {
        const int z = pass >> 1;
        const bool rows = (pass & 1) == 0;
        u64 R[16], I[16];

        if (rows) {
            const float* Vz = Vb + z * (512 * 512);
#pragma unroll
            for (int j = 0; j < 16; j++) {
                const int c = l8 + 8 * j;
                float wra, wrb, wia, wib;
                if (z == 0) {
                    wra = prm[lineA * 128 + c];   wrb = prm[lineB * 128 + c];
                    wia = pimm[lineA * 128 + c];  wib = pimm[lineB * 128 + c];
                } else {
                    wra = sRe[lineA * PITCH + c];  wrb = sRe[lineB * PITCH + c];
                    wia = sIm[lineA * PITCH + c];  wib = sIm[lineB * PITCH + c];
                }
                float va = Vz[lineA * 512 + c], vb = Vz[lineB * 512 + c];
                float sa, ca, sb, cb;
                __sincosf(va, &sa, &ca);
                __sincosf(vb, &sb, &cb);
                u64 wr = pk(wra, wrb), wi = pk(wia, wib);
                u64 cp = pk(ca, cb),  sp = pk(sa, sb);
                R[j] = f2sub(f2mul(wr, cp), f2mul(wi, sp));
                I[j] = f2fma(wr, sp, f2mul(wi, cp));
            }
        } else {
#pragma unroll
            for (int j = 0; j < 16; j++) {
                const int r = l8 + 8 * j;
                R[j] = pk(sRe[r * PITCH + lineA], sRe[r * PITCH + lineB]);
                I[j] = pk(sIm[r * PITCH + lineA], sIm[r * PITCH + lineB]);
            }
        }

        dif16(R, I, T);

        if (z < 7) {
#pragma unroll
            for (int j = 0; j < 16; j++)
                cmul_sc(R[j], I[j], Hr[j], Hi[j]);
            dit16(R, I, T);
        }

        if (pass == 15) {
            // detector intensity for this line-pair (bitrev storage order)
#pragma unroll
            for (int j = 0; j < 16; j++) {
                const int r = l8 + 8 * j;
                u64 mg = f2fma(R[j], R[j], f2mul(I[j], I[j]));
                float a, b; upk(mg, a, b);
                sRe[r * PITCH + lineA] = a;
                sRe[r * PITCH + lineB] = b;
            }
        } else if (rows) {
#pragma unroll
            for (int j = 0; j < 16; j++) {
                const int c = l8 + 8 * j;
                float a, b;
                upk(R[j], a, b);
                sRe[lineA * PITCH + c] = a;  sRe[lineB * PITCH + c] = b;
                upk(I[j], a, b);
                sIm[lineA * PITCH + c] = a;  sIm[lineB * PITCH + c] = b;
            }
        } else {
#pragma unroll
            for (int j = 0; j < 16; j++) {
                const int r = l8 + 8 * j;
                float a, b;
                upk(R[j], a, b);
                sRe[r * PITCH + lineA] = a;  sRe[r * PITCH + lineB] = b;
                upk(I[j], a, b);
                sIm[r * PITCH + lineA] = a;  sIm[r * PITCH + lineB] = b;
            }
        }
        __syncthreads();
    }

    // bitrev permute |psi|^2 to natural order, coalesced store to scratch
    float* out = g_int + ((size_t)bid << 14);
    for (int i = tid; i < 16384; i += 512) {
        const int y = i >> 7, x = i & 127;
        const int ry = (int)(__brev((unsigned)y) >> 25);
        const int rx = (int)(__brev((unsigned)x) >> 25);
        out[i] = sRe[ry * PITCH + rx];
    }
}

// ------------------------------ finalize ------------------------------------
__global__ void msp_finalize(float* __restrict__ outp)
{
    const size_t i = ((size_t)blockIdx.x * blockDim.x + threadIdx.x) * 4;
    float4 a = *(const float4*)(g_int + i);
    float4 b = *(const float4*)(g_int + i + ((size_t)1 << 22));
    float4 c = *(const float4*)(g_int + i + ((size_t)2 << 22));
    float4 d = *(const float4*)(g_int + i + ((size_t)3 << 22));
    float4 o;
    o.x = sqrtf(1e-10f + (a.x + b.x + c.x + d.x) * (1.0f / 16384.0f));
    o.y = sqrtf(1e-10f + (a.y + b.y + c.y + d.y) * (1.0f / 16384.0f));
    o.z = sqrtf(1e-10f + (a.z + b.z + c.z + d.z) * (1.0f / 16384.0f));
    o.w = sqrtf(1e-10f + (a.w + b.w + c.w + d.w) * (1.0f / 16384.0f));
    *(float4*)(outp + i) = o;
}

// ------------------------------ launcher ------------------------------------
extern "C" void kernel_launch(void* const* d_in, const int* in_sizes, int n_in,
                              void* d_out, int out_size)
{
    const float* V   = (const float*)d_in[0];
    const float* pre = (const float*)d_in[1];
    const float* pim = (const float*)d_in[2];
    const int*   pos = (const int*)d_in[3];
    float* out = (float*)d_out;
    (void)in_sizes; (void)n_in; (void)out_size;

    const size_t smem = SMEM_FLOATS * sizeof(float);   // 132096 B
    cudaFuncSetAttribute((const void*)msp_main,
                         cudaFuncAttributeMaxDynamicSharedMemorySize,
                         (int)smem);
    msp_main<<<1024, 512, smem>>>(V, pre, pim, pos);
    msp_finalize<<<4096, 256>>>(out);
}

// round 5
// speedup vs baseline: 1.2135x; 1.2135x over previous
#include <cuda_runtime.h>

// ---------------------------------------------------------------------------
// Multi-slice ptychography, fused, f32x2-packed, 4-shuffle-stage FFT.
// One CTA = one (mode,k). Wave in SMEM (pitch 129). Each 16-lane half-warp
// owns one f32x2-packed line pair with 8 values per lane (idx = l16 + 16j).
// FFT128: spans 64/32/16 register-local, spans 8/4/2/1 via shfl_xor.
// Register budget ~107 (cap 128 @ 512 thr) -- no spills, unlike the 16-val try.
// ---------------------------------------------------------------------------

typedef unsigned long long u64;

#define PITCH 129
#define SMEM_FLOATS (2 * 128 * PITCH)

static __device__ float g_int[4u * 256u * 128u * 128u];   // 64 MB scratch

// ----------------------------- f32x2 helpers --------------------------------
__device__ __forceinline__ u64 pk(float a, float b) {
    u64 r; asm("mov.b64 %0,{%1,%2};" : "=l"(r) : "f"(a), "f"(b)); return r;
}
__device__ __forceinline__ void upk(u64 v, float& a, float& b) {
    asm("mov.b64 {%0,%1},%2;" : "=f"(a), "=f"(b) : "l"(v));
}
__device__ __forceinline__ u64 f2add(u64 a, u64 b) {
    u64 d; asm("add.rn.f32x2 %0,%1,%2;" : "=l"(d) : "l"(a), "l"(b)); return d;
}
__device__ __forceinline__ u64 f2sub(u64 a, u64 b) {
    u64 d; asm("sub.rn.f32x2 %0,%1,%2;" : "=l"(d) : "l"(a), "l"(b)); return d;
}
__device__ __forceinline__ u64 f2mul(u64 a, u64 b) {
    u64 d; asm("mul.rn.f32x2 %0,%1,%2;" : "=l"(d) : "l"(a), "l"(b)); return d;
}
__device__ __forceinline__ u64 f2fma(u64 a, u64 b, u64 c) {
    u64 d; asm("fma.rn.f32x2 %0,%1,%2,%3;" : "=l"(d) : "l"(a), "l"(b), "l"(c)); return d;
}
__device__ __forceinline__ u64 f2neg(u64 v) {
    return v ^ 0x8000000080000000ull;
}
__device__ __forceinline__ u64 shx(u64 v, int s) {
    float a, b; upk(v, a, b);
    a = __shfl_xor_sync(0xffffffffu, a, s);
    b = __shfl_xor_sync(0xffffffffu, b, s);
    return pk(a, b);
}

// forward complex mult by scalar twiddle (tr, ti), broadcast to both halves
__device__ __forceinline__ void cmul_sc(u64& r, u64& i, float tr, float ti) {
    u64 Tr = pk(tr, tr), Ti = pk(ti, ti);
    u64 rr = f2sub(f2mul(r, Tr), f2mul(i, Ti));
    i = f2fma(r, Ti, f2mul(i, Tr));
    r = rr;
}
// conjugate complex mult by scalar twiddle (tr, ti)
__device__ __forceinline__ void cmulc_sc(u64& r, u64& i, float tr, float ti) {
    u64 Tr = pk(tr, tr), Ti = pk(ti, ti);
    u64 rr = f2fma(i, Ti, f2mul(r, Tr));
    i = f2sub(f2mul(i, Tr), f2mul(r, Ti));
    r = rr;
}

// ------------------------- twiddle context ----------------------------------
// W_e = exp(-2*pi*i*e/128), stored (c, -s). Per lane l16 = lane & 15.
struct Tw4 {
    float w64r[4], w64i[4];   // e = l16 + 16j, j=0..3      (span 64)
    float w32r[2], w32i[2];   // e = 2*l16 + 32j, j=0..1    (span 32)
    float w16r, w16i;         // e = 4*l16                  (span 16)
    u64 c8r, c8i;             // effective span-8 cross twiddle (hi lanes)
    u64 c4r, c4i;             // span-4
    u64 c2r, c2i;             // span-2
    u64 sg8, sg4, sg2, sg1;   // butterfly signs
};

__device__ __forceinline__ void cross_dif(u64 (&R)[8], u64 (&I)[8], int s,
                                          u64 sg, u64 cr, u64 ci)
{
    u64 nci = f2neg(ci);
#pragma unroll
    for (int j = 0; j < 8; j++) {
        u64 pR = shx(R[j], s), pI = shx(I[j], s);
        u64 xR = f2fma(sg, R[j], pR);
        u64 xI = f2fma(sg, I[j], pI);
        R[j] = f2fma(xI, nci, f2mul(xR, cr));
        I[j] = f2fma(xI, cr,  f2mul(xR, ci));
    }
}
__device__ __forceinline__ void cross_dit(u64 (&R)[8], u64 (&I)[8], int s,
                                          u64 sg, u64 cr, u64 ci)
{
    u64 nci = f2neg(ci);
#pragma unroll
    for (int j = 0; j < 8; j++) {
        u64 uR = f2fma(I[j], ci,  f2mul(R[j], cr));
        u64 uI = f2fma(R[j], nci, f2mul(I[j], cr));
        u64 pR = shx(uR, s), pI = shx(uI, s);
        R[j] = f2fma(sg, uR, pR);
        I[j] = f2fma(sg, uI, pI);
    }
}

__device__ __forceinline__ void dif8(u64 (&R)[8], u64 (&I)[8], const Tw4& T)
{
    // span 64: pairs (j, j+4), tw e = l16+16j
#pragma unroll
    for (int j = 0; j < 4; j++) {
        u64 dr = f2sub(R[j], R[j + 4]), di = f2sub(I[j], I[j + 4]);
        R[j] = f2add(R[j], R[j + 4]);  I[j] = f2add(I[j], I[j + 4]);
        R[j + 4] = dr;  I[j + 4] = di;
        cmul_sc(R[j + 4], I[j + 4], T.w64r[j], T.w64i[j]);
    }
    // span 32: pairs (b+j2, b+j2+2), tw e = 2*l16 + 32*j2
#pragma unroll
    for (int b = 0; b < 8; b += 4)
#pragma unroll
        for (int j2 = 0; j2 < 2; j2++) {
            int j = b + j2;
            u64 dr = f2sub(R[j], R[j + 2]), di = f2sub(I[j], I[j + 2]);
            R[j] = f2add(R[j], R[j + 2]);  I[j] = f2add(I[j], I[j + 2]);
            R[j + 2] = dr;  I[j + 2] = di;
            cmul_sc(R[j + 2], I[j + 2], T.w32r[j2], T.w32i[j2]);
        }
    // span 16: pairs (b, b+1), tw e = 4*l16
#pragma unroll
    for (int b = 0; b < 8; b += 2) {
        u64 dr = f2sub(R[b], R[b + 1]), di = f2sub(I[b], I[b + 1]);
        R[b] = f2add(R[b], R[b + 1]);  I[b] = f2add(I[b], I[b + 1]);
        R[b + 1] = dr;  I[b + 1] = di;
        cmul_sc(R[b + 1], I[b + 1], T.w16r, T.w16i);
    }
    // cross spans 8, 4, 2
    cross_dif(R, I, 8, T.sg8, T.c8r, T.c8i);
    cross_dif(R, I, 4, T.sg4, T.c4r, T.c4i);
    cross_dif(R, I, 2, T.sg2, T.c2r, T.c2i);
    // cross span 1 (no twiddle)
#pragma unroll
    for (int j = 0; j < 8; j++) {
        u64 pR = shx(R[j], 1), pI = shx(I[j], 1);
        R[j] = f2fma(T.sg1, R[j], pR);
        I[j] = f2fma(T.sg1, I[j], pI);
    }
}

// Inverse (unnormalized), bit-reversed input -> natural output.
__device__ __forceinline__ void dit8(u64 (&R)[8], u64 (&I)[8], const Tw4& T)
{
    // cross span 1
#pragma unroll
    for (int j = 0; j < 8; j++) {
        u64 pR = shx(R[j], 1), pI = shx(I[j], 1);
        R[j] = f2fma(T.sg1, R[j], pR);
        I[j] = f2fma(T.sg1, I[j], pI);
    }
    // cross spans 2, 4, 8 (conj effective twiddles)
    cross_dit(R, I, 2, T.sg2, T.c2r, T.c2i);
    cross_dit(R, I, 4, T.sg4, T.c4r, T.c4i);
    cross_dit(R, I, 8, T.sg8, T.c8r, T.c8i);
    // span 16
#pragma unroll
    for (int b = 0; b < 8; b += 2) {
        u64 br = R[b + 1], bi = I[b + 1];
        cmulc_sc(br, bi, T.w16r, T.w16i);
        R[b + 1] = f2sub(R[b], br);  I[b + 1] = f2sub(I[b], bi);
        R[b] = f2add(R[b], br);      I[b] = f2add(I[b], bi);
    }
    // span 32
#pragma unroll
    for (int b = 0; b < 8; b += 4)
#pragma unroll
        for (int j2 = 0; j2 < 2; j2++) {
            int j = b + j2;
            u64 br = R[j + 2], bi = I[j + 2];
            cmulc_sc(br, bi, T.w32r[j2], T.w32i[j2]);
            R[j + 2] = f2sub(R[j], br);  I[j + 2] = f2sub(I[j], bi);
            R[j] = f2add(R[j], br);      I[j] = f2add(I[j], bi);
        }
    // span 64
#pragma unroll
    for (int j = 0; j < 4; j++) {
        u64 br = R[j + 4], bi = I[j + 4];
        cmulc_sc(br, bi, T.w64r[j], T.w64i[j]);
        R[j + 4] = f2sub(R[j], br);  I[j + 4] = f2sub(I[j], bi);
        R[j] = f2add(R[j], br);      I[j] = f2add(I[j], bi);
    }
}

// ------------------------------- main kernel --------------------------------
__global__ void __launch_bounds__(512, 1)
msp_main(const float* __restrict__ V,
         const float* __restrict__ pre,
         const float* __restrict__ pim,
         const int*   __restrict__ ipos)
{
    extern __shared__ float smem[];
    float* sRe = smem;
    float* sIm = smem + 128 * PITCH;

    const int bid = blockIdx.x;
    const int k   = bid & 255;
    const int m   = bid >> 8;

    int py, px;
    {
        bool i64 = (ipos[1] | ipos[3] | ipos[5] | ipos[7] |
                    ipos[9] | ipos[11] | ipos[13] | ipos[15]) == 0;
        if (i64) { py = ipos[4 * k];  px = ipos[4 * k + 2]; }
        else     { py = ipos[2 * k];  px = ipos[2 * k + 1]; }
    }

    const int tid = threadIdx.x;
    const int l   = tid & 31;
    const int w   = tid >> 5;        // 16 warps
    const int l16 = l & 15;
    const int h   = l >> 4;          // half-warp index
    // lineA(h=1) = lineA(h=0) + 16 mod 32 -> conflict-free two-half stores
    const int baseLine = 2 * (w & 7) + 16 * h + 32 * (w >> 3);

    Tw4 T;
    {
#pragma unroll
        for (int j = 0; j < 4; j++) {
            float s, c; sincospif((float)(l16 + 16 * j) * (1.0f / 64.0f), &s, &c);
            T.w64r[j] = c;  T.w64i[j] = -s;
        }
#pragma unroll
        for (int j = 0; j < 2; j++) {
            float s, c; sincospif((float)(2 * l16 + 32 * j) * (1.0f / 64.0f), &s, &c);
            T.w32r[j] = c;  T.w32i[j] = -s;
        }
        { float s, c; sincospif((float)(4 * l16) * (1.0f / 64.0f), &s, &c);
          T.w16r = c;  T.w16i = -s; }
        { float s, c; sincospif((float)(8 * (l16 & 7)) * (1.0f / 64.0f), &s, &c);
          float tr = (l16 & 8) ? c : 1.0f, ti = (l16 & 8) ? -s : 0.0f;
          T.c8r = pk(tr, tr);  T.c8i = pk(ti, ti); }
        { float s, c; sincospif((float)(16 * (l16 & 3)) * (1.0f / 64.0f), &s, &c);
          float tr = (l16 & 4) ? c : 1.0f, ti = (l16 & 4) ? -s : 0.0f;
          T.c4r = pk(tr, tr);  T.c4i = pk(ti, ti); }
        { float s, c; sincospif((float)(32 * (l16 & 1)) * (1.0f / 64.0f), &s, &c);
          float tr = (l16 & 2) ? c : 1.0f, ti = (l16 & 2) ? -s : 0.0f;
          T.c2r = pk(tr, tr);  T.c2i = pk(ti, ti); }
        float s8 = (l16 & 8) ? -1.0f : 1.0f;  T.sg8 = pk(s8, s8);
        float s4 = (l16 & 4) ? -1.0f : 1.0f;  T.sg4 = pk(s4, s4);
        float s2 = (l16 & 2) ? -1.0f : 1.0f;  T.sg2 = pk(s2, s2);
        float s1 = (l16 & 1) ? -1.0f : 1.0f;  T.sg1 = pk(s1, s1);
    }

    // Fresnel factors at bit-reversed stored positions, 1/128 folded in
    float Hr[8], Hi[8];
#pragma unroll
    for (int j = 0; j < 8; j++) {
        int idx = l16 + 16 * j;
        int fb  = (int)(__brev((unsigned)idx) >> 25);
        float f = (float)(fb < 64 ? fb : fb - 128) * (1.0f / 25.6f);
        float s, c;
        sincospif(-0.25f * f * f, &s, &c);      // lambda*dz = 0.25
        Hr[j] = c * (1.0f / 128.0f);
        Hi[j] = s * (1.0f / 128.0f);
    }

    const float* Vb   = V + (py * 512 + px);
    const float* prm  = pre + m * 16384;
    const float* pimm = pim + m * 16384;

#pragma unroll 1
    for (int z = 0; z < 8; z++) {
        const float* Vz = Vb + z * (512 * 512);

        // ---------------- rows pass: transmit + DIF (+H+DIT if z<7) --------
#pragma unroll 1
        for (int p = 0; p < 2; p++) {
            const int lineA = baseLine + 64 * p, lineB = lineA + 1;
            u64 R[8], I[8];
#pragma unroll
            for (int j = 0; j < 8; j++) {
                const int c = l16 + 16 * j;
                float wra, wrb, wia, wib;
                if (z == 0) {
                    wra = prm[lineA * 128 + c];   wrb = prm[lineB * 128 + c];
                    wia = pimm[lineA * 128 + c];  wib = pimm[lineB * 128 + c];
                } else {
                    wra = sRe[lineA * PITCH + c];  wrb = sRe[lineB * PITCH + c];
                    wia = sIm[lineA * PITCH + c];  wib = sIm[lineB * PITCH + c];
                }
                float va = Vz[lineA * 512 + c], vb = Vz[lineB * 512 + c];
                float sa, ca, sb, cb;
                __sincosf(va, &sa, &ca);
                __sincosf(vb, &sb, &cb);
                u64 wr = pk(wra, wrb), wi = pk(wia, wib);
                u64 cp = pk(ca, cb),  sp = pk(sa, sb);
                R[j] = f2sub(f2mul(wr, cp), f2mul(wi, sp));
                I[j] = f2fma(wr, sp, f2mul(wi, cp));
            }
            dif8(R, I, T);
            if (z < 7) {
#pragma unroll
                for (int j = 0; j < 8; j++)
                    cmul_sc(R[j], I[j], Hr[j], Hi[j]);
                dit8(R, I, T);
            }
#pragma unroll
            for (int j = 0; j < 8; j++) {
                const int c = l16 + 16 * j;
                float a, b;
                upk(R[j], a, b);
                sRe[lineA * PITCH + c] = a;  sRe[lineB * PITCH + c] = b;
                upk(I[j], a, b);
                sIm[lineA * PITCH + c] = a;  sIm[lineB * PITCH + c] = b;
            }
        }
        __syncthreads();

        // ---------------- cols pass ----------------------------------------
#pragma unroll 1
        for (int p = 0; p < 2; p++) {
            const int lineA = baseLine + 64 * p, lineB = lineA + 1;
            u64 R[8], I[8];
#pragma unroll
            for (int j = 0; j < 8; j++) {
                const int r = l16 + 16 * j;
                R[j] = pk(sRe[r * PITCH + lineA], sRe[r * PITCH + lineB]);
                I[j] = pk(sIm[r * PITCH + lineA], sIm[r * PITCH + lineB]);
            }
            dif8(R, I, T);
            if (z < 7) {
#pragma unroll
                for (int j = 0; j < 8; j++)
                    cmul_sc(R[j], I[j], Hr[j], Hi[j]);
                dit8(R, I, T);
#pragma unroll
                for (int j = 0; j < 8; j++) {
                    const int r = l16 + 16 * j;
                    float a, b;
                    upk(R[j], a, b);
                    sRe[r * PITCH + lineA] = a;  sRe[r * PITCH + lineB] = b;
                    upk(I[j], a, b);
                    sIm[r * PITCH + lineA] = a;  sIm[r * PITCH + lineB] = b;
                }
            } else {
#pragma unroll
                for (int j = 0; j < 8; j++) {
                    const int r = l16 + 16 * j;
                    u64 mg = f2fma(R[j], R[j], f2mul(I[j], I[j]));
                    float a, b; upk(mg, a, b);
                    sRe[r * PITCH + lineA] = a;
                    sRe[r * PITCH + lineB] = b;
                }
            }
        }
        __syncthreads();
    }

    // bitrev permute |psi|^2 to natural order, coalesced store to scratch
    float* out = g_int + ((size_t)bid << 14);
    for (int i = tid; i < 16384; i += 512) {
        const int y = i >> 7, x = i & 127;
        const int ry = (int)(__brev((unsigned)y) >> 25);
        const int rx = (int)(__brev((unsigned)x) >> 25);
        out[i] = sRe[ry * PITCH + rx];
    }
}

// ------------------------------ finalize ------------------------------------
__global__ void msp_finalize(float* __restrict__ outp)
{
    const size_t i = ((size_t)blockIdx.x * blockDim.x + threadIdx.x) * 4;
    float4 a = *(const float4*)(g_int + i);
    float4 b = *(const float4*)(g_int + i + ((size_t)1 << 22));
    float4 c = *(const float4*)(g_int + i + ((size_t)2 << 22));
    float4 d = *(const float4*)(g_int + i + ((size_t)3 << 22));
    float4 o;
    o.x = sqrtf(1e-10f + (a.x + b.x + c.x + d.x) * (1.0f / 16384.0f));
    o.y = sqrtf(1e-10f + (a.y + b.y + c.y + d.y) * (1.0f / 16384.0f));
    o.z = sqrtf(1e-10f + (a.z + b.z + c.z + d.z) * (1.0f / 16384.0f));
    o.w = sqrtf(1e-10f + (a.w + b.w + c.w + d.w) * (1.0f / 16384.0f));
    *(float4*)(outp + i) = o;
}

// ------------------------------ launcher ------------------------------------
extern "C" void kernel_launch(void* const* d_in, const int* in_sizes, int n_in,
                              void* d_out, int out_size)
{
    const float* V   = (const float*)d_in[0];
    const float* pre = (const float*)d_in[1];
    const float* pim = (const float*)d_in[2];
    const int*   pos = (const int*)d_in[3];
    float* out = (float*)d_out;
    (void)in_sizes; (void)n_in; (void)out_size;

    const size_t smem = SMEM_FLOATS * sizeof(float);   // 132096 B
    cudaFuncSetAttribute((const void*)msp_main,
                         cudaFuncAttributeMaxDynamicSharedMemorySize,
                         (int)smem);
    msp_main<<<1024, 512, smem>>>(V, pre, pim, pos);
    msp_finalize<<<4096, 256>>>(out);
}

// round 8
// speedup vs baseline: 1.2435x; 1.0247x over previous
#include <cuda_runtime.h>

// ---------------------------------------------------------------------------
// Multi-slice ptychography, fused, f32x2-packed, 4-shuffle-stage FFT.
// One CTA = one (mode,k). Wave in SMEM (pitch 129). Each 16-lane half-warp
// owns one f32x2-packed line pair with 8 values per lane (idx = l16 + 16j).
// Register stages = twiddle-free DFT-8 (cheap constant twiddles; -i via XOR)
// followed by a single outer twiddle W_128^(l16*br3(s)) per slot.
// Cross-lane spans 8/4/2/1 via shfl_xor.
// ---------------------------------------------------------------------------

typedef unsigned long long u64;

#define PITCH 129
#define SMEM_FLOATS (2 * 128 * PITCH)
#define RSQRT2 0.70710678118654752440f

static __device__ float g_int[4u * 256u * 128u * 128u];   // 64 MB scratch

// ----------------------------- f32x2 helpers --------------------------------
__device__ __forceinline__ u64 pk(float a, float b) {
    u64 r; asm("mov.b64 %0,{%1,%2};" : "=l"(r) : "f"(a), "f"(b)); return r;
}
__device__ __forceinline__ void upk(u64 v, float& a, float& b) {
    asm("mov.b64 {%0,%1},%2;" : "=f"(a), "=f"(b) : "l"(v));
}
__device__ __forceinline__ u64 f2add(u64 a, u64 b) {
    u64 d; asm("add.rn.f32x2 %0,%1,%2;" : "=l"(d) : "l"(a), "l"(b)); return d;
}
__device__ __forceinline__ u64 f2sub(u64 a, u64 b) {
    u64 d; asm("sub.rn.f32x2 %0,%1,%2;" : "=l"(d) : "l"(a), "l"(b)); return d;
}
__device__ __forceinline__ u64 f2mul(u64 a, u64 b) {
    u64 d; asm("mul.rn.f32x2 %0,%1,%2;" : "=l"(d) : "l"(a), "l"(b)); return d;
}
__device__ __forceinline__ u64 f2fma(u64 a, u64 b, u64 c) {
    u64 d; asm("fma.rn.f32x2 %0,%1,%2,%3;" : "=l"(d) : "l"(a), "l"(b), "l"(c)); return d;
}
__device__ __forceinline__ u64 f2neg(u64 v) {
    return v ^ 0x8000000080000000ull;
}
__device__ __forceinline__ u64 shx(u64 v, int s) {
    float a, b; upk(v, a, b);
    a = __shfl_xor_sync(0xffffffffu, a, s);
    b = __shfl_xor_sync(0xffffffffu, b, s);
    return pk(a, b);
}

// forward complex mult by scalar twiddle (tr, ti), broadcast to both halves
__device__ __forceinline__ void cmul_sc(u64& r, u64& i, float tr, float ti) {
    u64 Tr = pk(tr, tr), Ti = pk(ti, ti);
    u64 rr = f2sub(f2mul(r, Tr), f2mul(i, Ti));
    i = f2fma(r, Ti, f2mul(i, Tr));
    r = rr;
}
// conjugate complex mult by scalar twiddle (tr, ti)
__device__ __forceinline__ void cmulc_sc(u64& r, u64& i, float tr, float ti) {
    u64 Tr = pk(tr, tr), Ti = pk(ti, ti);
    u64 rr = f2fma(i, Ti, f2mul(r, Tr));
    i = f2sub(f2mul(i, Tr), f2mul(r, Ti));
    r = rr;
}

// ------------------------- twiddle context ----------------------------------
// W_e = exp(-2*pi*i*e/128), stored (c, -s). Per lane l16 = lane & 15.
struct Tw4 {
    float owr[8], owi[8];     // outer twiddles W^(l16*t), t=1..7 (t=0 unused)
    u64 K;                    // (1/sqrt2, 1/sqrt2)
    u64 c8r, c8i;             // effective span-8 cross twiddle (hi lanes)
    u64 c4r, c4i;             // span-4
    u64 c2r, c2i;             // span-2
    u64 sg8, sg4, sg2, sg1;   // butterfly signs
};

__device__ __forceinline__ void cross_dif(u64 (&R)[8], u64 (&I)[8], int s,
                                          u64 sg, u64 cr, u64 ci)
{
    u64 nci = f2neg(ci);
#pragma unroll
    for (int j = 0; j < 8; j++) {
        u64 pR = shx(R[j], s), pI = shx(I[j], s);
        u64 xR = f2fma(sg, R[j], pR);
        u64 xI = f2fma(sg, I[j], pI);
        R[j] = f2fma(xI, nci, f2mul(xR, cr));
        I[j] = f2fma(xI, cr,  f2mul(xR, ci));
    }
}
__device__ __forceinline__ void cross_dit(u64 (&R)[8], u64 (&I)[8], int s,
                                          u64 sg, u64 cr, u64 ci)
{
    u64 nci = f2neg(ci);
#pragma unroll
    for (int j = 0; j < 8; j++) {
        u64 uR = f2fma(I[j], ci,  f2mul(R[j], cr));
        u64 uI = f2fma(R[j], nci, f2mul(I[j], cr));
        u64 pR = shx(uR, s), pI = shx(uI, s);
        R[j] = f2fma(sg, uR, pR);
        I[j] = f2fma(sg, uI, pI);
    }
}

__device__ __forceinline__ void dif8(u64 (&R)[8], u64 (&I)[8], const Tw4& T)
{
    // ---- DFT-8 stage A (span 4), internal twiddles W_8^j ----
    {
        u64 dr, di;
        dr = f2sub(R[0], R[4]);  di = f2sub(I[0], I[4]);
        R[0] = f2add(R[0], R[4]);  I[0] = f2add(I[0], I[4]);
        R[4] = dr;  I[4] = di;                                   // W_8^0 = 1
        dr = f2sub(R[1], R[5]);  di = f2sub(I[1], I[5]);
        R[1] = f2add(R[1], R[5]);  I[1] = f2add(I[1], I[5]);
        R[5] = f2mul(f2add(dr, di), T.K);                        // (1-i)/sqrt2
        I[5] = f2mul(f2sub(di, dr), T.K);
        dr = f2sub(R[2], R[6]);  di = f2sub(I[2], I[6]);
        R[2] = f2add(R[2], R[6]);  I[2] = f2add(I[2], I[6]);
        R[6] = di;  I[6] = f2neg(dr);                            // * -i
        dr = f2sub(R[3], R[7]);  di = f2sub(I[3], I[7]);
        R[3] = f2add(R[3], R[7]);  I[3] = f2add(I[3], I[7]);
        R[7] = f2mul(f2sub(di, dr), T.K);                        // -(1+i)/sqrt2
        I[7] = f2mul(f2neg(f2add(dr, di)), T.K);
    }
    // ---- stage B (span 2): pairs (0,2),(4,6) plain; (1,3),(5,7) bot * -i ----
    {
        u64 dr, di;
        dr = f2sub(R[0], R[2]);  di = f2sub(I[0], I[2]);
        R[0] = f2add(R[0], R[2]);  I[0] = f2add(I[0], I[2]);
        R[2] = dr;  I[2] = di;
        dr = f2sub(R[4], R[6]);  di = f2sub(I[4], I[6]);
        R[4] = f2add(R[4], R[6]);  I[4] = f2add(I[4], I[6]);
        R[6] = dr;  I[6] = di;
        dr = f2sub(R[1], R[3]);  di = f2sub(I[1], I[3]);
        R[1] = f2add(R[1], R[3]);  I[1] = f2add(I[1], I[3]);
        R[3] = di;  I[3] = f2neg(dr);                            // * -i
        dr = f2sub(R[5], R[7]);  di = f2sub(I[5], I[7]);
        R[5] = f2add(R[5], R[7]);  I[5] = f2add(I[5], I[7]);
        R[7] = di;  I[7] = f2neg(dr);                            // * -i
    }
    // ---- stage C (span 1): plain butterflies ----
#pragma unroll
    for (int b = 0; b < 8; b += 2) {
        u64 dr = f2sub(R[b], R[b + 1]), di = f2sub(I[b], I[b + 1]);
        R[b] = f2add(R[b], R[b + 1]);  I[b] = f2add(I[b], I[b + 1]);
        R[b + 1] = dr;  I[b + 1] = di;
    }
    // ---- outer twiddles: slot s gets W^(l16 * br3(s)) ----
    cmul_sc(R[1], I[1], T.owr[4], T.owi[4]);
    cmul_sc(R[2], I[2], T.owr[2], T.owi[2]);
    cmul_sc(R[3], I[3], T.owr[6], T.owi[6]);
    cmul_sc(R[4], I[4], T.owr[1], T.owi[1]);
    cmul_sc(R[5], I[5], T.owr[5], T.owi[5]);
    cmul_sc(R[6], I[6], T.owr[3], T.owi[3]);
    cmul_sc(R[7], I[7], T.owr[7], T.owi[7]);
    // ---- cross spans 8, 4, 2 ----
    cross_dif(R, I, 8, T.sg8, T.c8r, T.c8i);
    cross_dif(R, I, 4, T.sg4, T.c4r, T.c4i);
    cross_dif(R, I, 2, T.sg2, T.c2r, T.c2i);
    // ---- cross span 1 (no twiddle) ----
#pragma unroll
    for (int j = 0; j < 8; j++) {
        u64 pR = shx(R[j], 1), pI = shx(I[j], 1);
        R[j] = f2fma(T.sg1, R[j], pR);
        I[j] = f2fma(T.sg1, I[j], pI);
    }
}

// Inverse (unnormalized), bit-reversed input -> natural output.
__device__ __forceinline__ void dit8(u64 (&R)[8], u64 (&I)[8], const Tw4& T)
{
    // ---- cross span 1 ----
#pragma unroll
    for (int j = 0; j < 8; j++) {
        u64 pR = shx(R[j], 1), pI = shx(I[j], 1);
        R[j] = f2fma(T.sg1, R[j], pR);
        I[j] = f2fma(T.sg1, I[j], pI);
    }
    // ---- cross spans 2, 4, 8 (conj effective twiddles) ----
    cross_dit(R, I, 2, T.sg2, T.c2r, T.c2i);
    cross_dit(R, I, 4, T.sg4, T.c4r, T.c4i);
    cross_dit(R, I, 8, T.sg8, T.c8r, T.c8i);
    // ---- outer conj twiddles ----
    cmulc_sc(R[1], I[1], T.owr[4], T.owi[4]);
    cmulc_sc(R[2], I[2], T.owr[2], T.owi[2]);
    cmulc_sc(R[3], I[3], T.owr[6], T.owi[6]);
    cmulc_sc(R[4], I[4], T.owr[1], T.owi[1]);
    cmulc_sc(R[5], I[5], T.owr[5], T.owi[5]);
    cmulc_sc(R[6], I[6], T.owr[3], T.owi[3]);
    cmulc_sc(R[7], I[7], T.owr[7], T.owi[7]);
    // ---- stage C' (span 1): plain ----
#pragma unroll
    for (int b = 0; b < 8; b += 2) {
        u64 br = R[b + 1], bi = I[b + 1];
        R[b + 1] = f2sub(R[b], br);  I[b + 1] = f2sub(I[b], bi);
        R[b] = f2add(R[b], br);      I[b] = f2add(I[b], bi);
    }
    // ---- stage B' (span 2): slots 3,7 * i, then plain butterflies ----
    {
        u64 t;
        t = f2neg(I[3]);  I[3] = R[3];  R[3] = t;                // * i
        t = f2neg(I[7]);  I[7] = R[7];  R[7] = t;                // * i
        u64 br, bi;
        br = R[2];  bi = I[2];
        R[2] = f2sub(R[0], br);  I[2] = f2sub(I[0], bi);
        R[0] = f2add(R[0], br);  I[0] = f2add(I[0], bi);
        br = R[3];  bi = I[3];
        R[3] = f2sub(R[1], br);  I[3] = f2sub(I[1], bi);
        R[1] = f2add(R[1], br);  I[1] = f2add(I[1], bi);
        br = R[6];  bi = I[6];
        R[6] = f2sub(R[4], br);  I[6] = f2sub(I[4], bi);
        R[4] = f2add(R[4], br);  I[4] = f2add(I[4], bi);
        br = R[7];  bi = I[7];
        R[7] = f2sub(R[5], br);  I[7] = f2sub(I[5], bi);
        R[5] = f2add(R[5], br);  I[5] = f2add(I[5], bi);
    }
    // ---- stage A' (span 4): conj internal twiddles, then butterflies ----
    {
        u64 nr, ni, t;
        nr = f2mul(f2sub(R[5], I[5]), T.K);                      // * (1+i)/sqrt2
        ni = f2mul(f2add(R[5], I[5]), T.K);
        R[5] = nr;  I[5] = ni;
        t = f2neg(I[6]);  I[6] = R[6];  R[6] = t;                // * i
        nr = f2mul(f2neg(f2add(R[7], I[7])), T.K);               // * (-1+i)/sqrt2
        ni = f2mul(f2sub(R[7], I[7]), T.K);
        R[7] = nr;  I[7] = ni;
#pragma unroll
        for (int j = 0; j < 4; j++) {
            u64 br = R[j + 4], bi = I[j + 4];
            R[j + 4] = f2sub(R[j], br);  I[j + 4] = f2sub(I[j], bi);
            R[j] = f2add(R[j], br);      I[j] = f2add(I[j], bi);
        }
    }
}

// ------------------------------- main kernel --------------------------------
__global__ void __launch_bounds__(512, 1)
msp_main(const float* __restrict__ V,
         const float* __restrict__ pre,
         const float* __restrict__ pim,
         const int*   __restrict__ ipos)
{
    extern __shared__ float smem[];
    float* sRe = smem;
    float* sIm = smem + 128 * PITCH;

    const int bid = blockIdx.x;
    const int k   = bid & 255;
    const int m   = bid >> 8;

    int py, px;
    {
        bool i64 = (ipos[1] | ipos[3] | ipos[5] | ipos[7] |
                    ipos[9] | ipos[11] | ipos[13] | ipos[15]) == 0;
        if (i64) { py = ipos[4 * k];  px = ipos[4 * k + 2]; }
        else     { py = ipos[2 * k];  px = ipos[2 * k + 1]; }
    }

    const int tid = threadIdx.x;
    const int l   = tid & 31;
    const int w   = tid >> 5;        // 16 warps
    const int l16 = l & 15;
    const int h   = l >> 4;          // half-warp index
    // lineA(h=1) = lineA(h=0) + 16 mod 32 -> conflict-free two-half stores
    const int baseLine = 2 * (w & 7) + 16 * h + 32 * (w >> 3);

    Tw4 T;
    {
        T.owr[0] = 1.0f;  T.owi[0] = 0.0f;
#pragma unroll
        for (int t = 1; t < 8; t++) {
            float s, c; sincospif((float)(l16 * t) * (1.0f / 64.0f), &s, &c);
            T.owr[t] = c;  T.owi[t] = -s;
        }
        T.K = pk(RSQRT2, RSQRT2);
        { float s, c; sincospif((float)(8 * (l16 & 7)) * (1.0f / 64.0f), &s, &c);
          float tr = (l16 & 8) ? c : 1.0f, ti = (l16 & 8) ? -s : 0.0f;
          T.c8r = pk(tr, tr);  T.c8i = pk(ti, ti); }
        { float s, c; sincospif((float)(16 * (l16 & 3)) * (1.0f / 64.0f), &s, &c);
          float tr = (l16 & 4) ? c : 1.0f, ti = (l16 & 4) ? -s : 0.0f;
          T.c4r = pk(tr, tr);  T.c4i = pk(ti, ti); }
        { float s, c; sincospif((float)(32 * (l16 & 1)) * (1.0f / 64.0f), &s, &c);
          float tr = (l16 & 2) ? c : 1.0f, ti = (l16 & 2) ? -s : 0.0f;
          T.c2r = pk(tr, tr);  T.c2i = pk(ti, ti); }
        float s8 = (l16 & 8) ? -1.0f : 1.0f;  T.sg8 = pk(s8, s8);
        float s4 = (l16 & 4) ? -1.0f : 1.0f;  T.sg4 = pk(s4, s4);
        float s2 = (l16 & 2) ? -1.0f : 1.0f;  T.sg2 = pk(s2, s2);
        float s1 = (l16 & 1) ? -1.0f : 1.0f;  T.sg1 = pk(s1, s1);
    }

    // Fresnel factors at bit-reversed stored positions, 1/128 folded in
    float Hr[8], Hi[8];
#pragma unroll
    for (int j = 0; j < 8; j++) {
        int idx = l16 + 16 * j;
        int fb  = (int)(__brev((unsigned)idx) >> 25);
        float f = (float)(fb < 64 ? fb : fb - 128) * (1.0f / 25.6f);
        float s, c;
        sincospif(-0.25f * f * f, &s, &c);      // lambda*dz = 0.25
        Hr[j] = c * (1.0f / 128.0f);
        Hi[j] = s * (1.0f / 128.0f);
    }

    const float* Vb   = V + (py * 512 + px);
    const float* prm  = pre + m * 16384;
    const float* pimm = pim + m * 16384;

#pragma unroll 1
    for (int z = 0; z < 8; z++) {
        const float* Vz = Vb + z * (512 * 512);

        // ---------------- rows pass: transmit + DIF (+H+DIT if z<7) --------
#pragma unroll 1
        for (int p = 0; p < 2; p++) {
            const int lineA = baseLine + 64 * p, lineB = lineA + 1;
            u64 R[8], I[8];
#pragma unroll
            for (int j = 0; j < 8; j++) {
                const int c = l16 + 16 * j;
                float wra, wrb, wia, wib;
                if (z == 0) {
                    wra = prm[lineA * 128 + c];   wrb = prm[lineB * 128 + c];
                    wia = pimm[lineA * 128 + c];  wib = pimm[lineB * 128 + c];
                } else {
                    wra = sRe[lineA * PITCH + c];  wrb = sRe[lineB * PITCH + c];
                    wia = sIm[lineA * PITCH + c];  wib = sIm[lineB * PITCH + c];
                }
                float va = Vz[lineA * 512 + c], vb = Vz[lineB * 512 + c];
                float sa, ca, sb, cb;
                __sincosf(va, &sa, &ca);
                __sincosf(vb, &sb, &cb);
                u64 wr = pk(wra, wrb), wi = pk(wia, wib);
                u64 cp = pk(ca, cb),  sp = pk(sa, sb);
                R[j] = f2sub(f2mul(wr, cp), f2mul(wi, sp));
                I[j] = f2fma(wr, sp, f2mul(wi, cp));
            }
            dif8(R, I, T);
            if (z < 7) {
#pragma unroll
                for (int j = 0; j < 8; j++)
                    cmul_sc(R[j], I[j], Hr[j], Hi[j]);
                dit8(R, I, T);
            }
#pragma unroll
            for (int j = 0; j < 8; j++) {
                const int c = l16 + 16 * j;
                float a, b;
                upk(R[j], a, b);
                sRe[lineA * PITCH + c] = a;  sRe[lineB * PITCH + c] = b;
                upk(I[j], a, b);
                sIm[lineA * PITCH + c] = a;  sIm[lineB * PITCH + c] = b;
            }
        }
        __syncthreads();

        // ---------------- cols pass ----------------------------------------
#pragma unroll 1
        for (int p = 0; p < 2; p++) {
            const int lineA = baseLine + 64 * p, lineB = lineA + 1;
            u64 R[8], I[8];
#pragma unroll
            for (int j = 0; j < 8; j++) {
                const int r = l16 + 16 * j;
                R[j] = pk(sRe[r * PITCH + lineA], sRe[r * PITCH + lineB]);
                I[j] = pk(sIm[r * PITCH + lineA], sIm[r * PITCH + lineB]);
            }
            dif8(R, I, T);
            if (z < 7) {
#pragma unroll
                for (int j = 0; j < 8; j++)
                    cmul_sc(R[j], I[j], Hr[j], Hi[j]);
                dit8(R, I, T);
#pragma unroll
                for (int j = 0; j < 8; j++) {
                    const int r = l16 + 16 * j;
                    float a, b;
                    upk(R[j], a, b);
                    sRe[r * PITCH + lineA] = a;  sRe[r * PITCH + lineB] = b;
                    upk(I[j], a, b);
                    sIm[r * PITCH + lineA] = a;  sIm[r * PITCH + lineB] = b;
                }
            } else {
#pragma unroll
                for (int j = 0; j < 8; j++) {
                    const int r = l16 + 16 * j;
                    u64 mg = f2fma(R[j], R[j], f2mul(I[j], I[j]));
                    float a, b; upk(mg, a, b);
                    sRe[r * PITCH + lineA] = a;
                    sRe[r * PITCH + lineB] = b;
                }
            }
        }
        __syncthreads();
    }

    // bitrev permute |psi|^2 to natural order, vectorized STG.128
    {
        float4* out4 = (float4*)(g_int + ((size_t)bid << 14));
        for (int i = tid; i < 4096; i += 512) {
            const int y = i >> 5;                 // natural row
            const int q = i & 31;                 // x-group (4 cols)
            const int ry = (int)(__brev((unsigned)y) >> 25);
            const int bx = (int)(__brev((unsigned)q) >> 27);  // br7(4q) = br5(q)
            float4 v;
            v.x = sRe[ry * PITCH + bx];
            v.y = sRe[ry * PITCH + bx + 64];
            v.z = sRe[ry * PITCH + bx + 32];
            v.w = sRe[ry * PITCH + bx + 96];
            out4[i] = v;
        }
    }
}

// ------------------------------ finalize ------------------------------------
__global__ void msp_finalize(float* __restrict__ outp)
{
    const size_t i = ((size_t)blockIdx.x * blockDim.x + threadIdx.x) * 4;
    float4 a = *(const float4*)(g_int + i);
    float4 b = *(const float4*)(g_int + i + ((size_t)1 << 22));
    float4 c = *(const float4*)(g_int + i + ((size_t)2 << 22));
    float4 d = *(const float4*)(g_int + i + ((size_t)3 << 22));
    float4 o;
    o.x = sqrtf(1e-10f + (a.x + b.x + c.x + d.x) * (1.0f / 16384.0f));
    o.y = sqrtf(1e-10f + (a.y + b.y + c.y + d.y) * (1.0f / 16384.0f));
    o.z = sqrtf(1e-10f + (a.z + b.z + c.z + d.z) * (1.0f / 16384.0f));
    o.w = sqrtf(1e-10f + (a.w + b.w + c.w + d.w) * (1.0f / 16384.0f));
    *(float4*)(outp + i) = o;
}

// ------------------------------ launcher ------------------------------------
extern "C" void kernel_launch(void* const* d_in, const int* in_sizes, int n_in,
                              void* d_out, int out_size)
{
    const float* V   = (const float*)d_in[0];
    const float* pre = (const float*)d_in[1];
    const float* pim = (const float*)d_in[2];
    const int*   pos = (const int*)d_in[3];
    float* out = (float*)d_out;
    (void)in_sizes; (void)n_in; (void)out_size;

    const size_t smem = SMEM_FLOATS * sizeof(float);   // 132096 B
    cudaFuncSetAttribute((const void*)msp_main,
                         cudaFuncAttributeMaxDynamicSharedMemorySize,
                         (int)smem);
    msp_main<<<1024, 512, smem>>>(V, pre, pim, pos);
    msp_finalize<<<4096, 256>>>(out);
}

// round 9
// speedup vs baseline: 1.3625x; 1.0957x over previous
#include <cuda_runtime.h>

// ---------------------------------------------------------------------------
// Multi-slice ptychography, fused, f32x2-packed, pass-fused (10 passes).
// Row-conv and col-conv commute within a slice, so slices alternate
// orientation and adjacent same-orientation convs share one SMEM round trip:
//   R T0 | C T1 C | R T2 R | C T3 C | R T4 R | C T5 C | R T6 R | C | T7 Fr | Fc
// Transmission T = exp(iV) precomputed (row-major + transposed, float2) so
// every transmit is one coalesced LDG.64 + cmul (no sincos in main loop).
// FFT128: DFT-8 register stages + outer twiddles, cross spans 8/4/2/1 shfl.
// ---------------------------------------------------------------------------

typedef unsigned long long u64;

#define PITCH 129
#define SMEM_FLOATS (2 * 128 * PITCH)
#define RSQRT2 0.70710678118654752440f

static __device__ float  g_int[4u * 256u * 128u * 128u];    // 64 MB scratch
static __device__ float2 g_trow[8u * 512u * 512u];          // 16 MB T row-major
static __device__ float2 g_tcol[8u * 512u * 512u];          // 16 MB T transposed

// ----------------------------- f32x2 helpers --------------------------------
__device__ __forceinline__ u64 pk(float a, float b) {
    u64 r; asm("mov.b64 %0,{%1,%2};" : "=l"(r) : "f"(a), "f"(b)); return r;
}
__device__ __forceinline__ void upk(u64 v, float& a, float& b) {
    asm("mov.b64 {%0,%1},%2;" : "=f"(a), "=f"(b) : "l"(v));
}
__device__ __forceinline__ u64 f2add(u64 a, u64 b) {
    u64 d; asm("add.rn.f32x2 %0,%1,%2;" : "=l"(d) : "l"(a), "l"(b)); return d;
}
__device__ __forceinline__ u64 f2sub(u64 a, u64 b) {
    u64 d; asm("sub.rn.f32x2 %0,%1,%2;" : "=l"(d) : "l"(a), "l"(b)); return d;
}
__device__ __forceinline__ u64 f2mul(u64 a, u64 b) {
    u64 d; asm("mul.rn.f32x2 %0,%1,%2;" : "=l"(d) : "l"(a), "l"(b)); return d;
}
__device__ __forceinline__ u64 f2fma(u64 a, u64 b, u64 c) {
    u64 d; asm("fma.rn.f32x2 %0,%1,%2,%3;" : "=l"(d) : "l"(a), "l"(b), "l"(c)); return d;
}
__device__ __forceinline__ u64 f2neg(u64 v) {
    return v ^ 0x8000000080000000ull;
}
__device__ __forceinline__ u64 shx(u64 v, int s) {
    float a, b; upk(v, a, b);
    a = __shfl_xor_sync(0xffffffffu, a, s);
    b = __shfl_xor_sync(0xffffffffu, b, s);
    return pk(a, b);
}

__device__ __forceinline__ void cmul_sc(u64& r, u64& i, float tr, float ti) {
    u64 Tr = pk(tr, tr), Ti = pk(ti, ti);
    u64 rr = f2sub(f2mul(r, Tr), f2mul(i, Ti));
    i = f2fma(r, Ti, f2mul(i, Tr));
    r = rr;
}
__device__ __forceinline__ void cmulc_sc(u64& r, u64& i, float tr, float ti) {
    u64 Tr = pk(tr, tr), Ti = pk(ti, ti);
    u64 rr = f2fma(i, Ti, f2mul(r, Tr));
    i = f2sub(f2mul(i, Tr), f2mul(r, Ti));
    r = rr;
}

// ------------------------- twiddle context ----------------------------------
struct Tw4 {
    float owr[8], owi[8];     // outer twiddles W^(l16*t)
    u64 K;                    // (1/sqrt2, 1/sqrt2)
    u64 c8r, c8i, c4r, c4i, c2r, c2i;   // effective cross twiddles (hi lanes)
    u64 sg8, sg4, sg2, sg1;   // butterfly signs
};

__device__ __forceinline__ void cross_dif(u64 (&R)[8], u64 (&I)[8], int s,
                                          u64 sg, u64 cr, u64 ci)
{
    u64 nci = f2neg(ci);
#pragma unroll
    for (int j = 0; j < 8; j++) {
        u64 pR = shx(R[j], s), pI = shx(I[j], s);
        u64 xR = f2fma(sg, R[j], pR);
        u64 xI = f2fma(sg, I[j], pI);
        R[j] = f2fma(xI, nci, f2mul(xR, cr));
        I[j] = f2fma(xI, cr,  f2mul(xR, ci));
    }
}
__device__ __forceinline__ void cross_dit(u64 (&R)[8], u64 (&I)[8], int s,
                                          u64 sg, u64 cr, u64 ci)
{
    u64 nci = f2neg(ci);
#pragma unroll
    for (int j = 0; j < 8; j++) {
        u64 uR = f2fma(I[j], ci,  f2mul(R[j], cr));
        u64 uI = f2fma(R[j], nci, f2mul(I[j], cr));
        u64 pR = shx(uR, s), pI = shx(uI, s);
        R[j] = f2fma(sg, uR, pR);
        I[j] = f2fma(sg, uI, pI);
    }
}

__device__ __forceinline__ void dif8(u64 (&R)[8], u64 (&I)[8], const Tw4& T)
{
    // DFT-8 stage A (span 4), internal twiddles W_8^j
    {
        u64 dr, di;
        dr = f2sub(R[0], R[4]);  di = f2sub(I[0], I[4]);
        R[0] = f2add(R[0], R[4]);  I[0] = f2add(I[0], I[4]);
        R[4] = dr;  I[4] = di;
        dr = f2sub(R[1], R[5]);  di = f2sub(I[1], I[5]);
        R[1] = f2add(R[1], R[5]);  I[1] = f2add(I[1], I[5]);
        R[5] = f2mul(f2add(dr, di), T.K);
        I[5] = f2mul(f2sub(di, dr), T.K);
        dr = f2sub(R[2], R[6]);  di = f2sub(I[2], I[6]);
        R[2] = f2add(R[2], R[6]);  I[2] = f2add(I[2], I[6]);
        R[6] = di;  I[6] = f2neg(dr);
        dr = f2sub(R[3], R[7]);  di = f2sub(I[3], I[7]);
        R[3] = f2add(R[3], R[7]);  I[3] = f2add(I[3], I[7]);
        R[7] = f2mul(f2sub(di, dr), T.K);
        I[7] = f2mul(f2neg(f2add(dr, di)), T.K);
    }
    // stage B (span 2)
    {
        u64 dr, di;
        dr = f2sub(R[0], R[2]);  di = f2sub(I[0], I[2]);
        R[0] = f2add(R[0], R[2]);  I[0] = f2add(I[0], I[2]);
        R[2] = dr;  I[2] = di;
        dr = f2sub(R[4], R[6]);  di = f2sub(I[4], I[6]);
        R[4] = f2add(R[4], R[6]);  I[4] = f2add(I[4], I[6]);
        R[6] = dr;  I[6] = di;
        dr = f2sub(R[1], R[3]);  di = f2sub(I[1], I[3]);
        R[1] = f2add(R[1], R[3]);  I[1] = f2add(I[1], I[3]);
        R[3] = di;  I[3] = f2neg(dr);
        dr = f2sub(R[5], R[7]);  di = f2sub(I[5], I[7]);
        R[5] = f2add(R[5], R[7]);  I[5] = f2add(I[5], I[7]);
        R[7] = di;  I[7] = f2neg(dr);
    }
    // stage C (span 1)
#pragma unroll
    for (int b = 0; b < 8; b += 2) {
        u64 dr = f2sub(R[b], R[b + 1]), di = f2sub(I[b], I[b + 1]);
        R[b] = f2add(R[b], R[b + 1]);  I[b] = f2add(I[b], I[b + 1]);
        R[b + 1] = dr;  I[b + 1] = di;
    }
    // outer twiddles W^(l16 * br3(s))
    cmul_sc(R[1], I[1], T.owr[4], T.owi[4]);
    cmul_sc(R[2], I[2], T.owr[2], T.owi[2]);
    cmul_sc(R[3], I[3], T.owr[6], T.owi[6]);
    cmul_sc(R[4], I[4], T.owr[1], T.owi[1]);
    cmul_sc(R[5], I[5], T.owr[5], T.owi[5]);
    cmul_sc(R[6], I[6], T.owr[3], T.owi[3]);
    cmul_sc(R[7], I[7], T.owr[7], T.owi[7]);
    // cross spans 8,4,2
    cross_dif(R, I, 8, T.sg8, T.c8r, T.c8i);
    cross_dif(R, I, 4, T.sg4, T.c4r, T.c4i);
    cross_dif(R, I, 2, T.sg2, T.c2r, T.c2i);
    // cross span 1
#pragma unroll
    for (int j = 0; j < 8; j++) {
        u64 pR = shx(R[j], 1), pI = shx(I[j], 1);
        R[j] = f2fma(T.sg1, R[j], pR);
        I[j] = f2fma(T.sg1, I[j], pI);
    }
}

__device__ __forceinline__ void dit8(u64 (&R)[8], u64 (&I)[8], const Tw4& T)
{
#pragma unroll
    for (int j = 0; j < 8; j++) {
        u64 pR = shx(R[j], 1), pI = shx(I[j], 1);
        R[j] = f2fma(T.sg1, R[j], pR);
        I[j] = f2fma(T.sg1, I[j], pI);
    }
    cross_dit(R, I, 2, T.sg2, T.c2r, T.c2i);
    cross_dit(R, I, 4, T.sg4, T.c4r, T.c4i);
    cross_dit(R, I, 8, T.sg8, T.c8r, T.c8i);
    cmulc_sc(R[1], I[1], T.owr[4], T.owi[4]);
    cmulc_sc(R[2], I[2], T.owr[2], T.owi[2]);
    cmulc_sc(R[3], I[3], T.owr[6], T.owi[6]);
    cmulc_sc(R[4], I[4], T.owr[1], T.owi[1]);
    cmulc_sc(R[5], I[5], T.owr[5], T.owi[5]);
    cmulc_sc(R[6], I[6], T.owr[3], T.owi[3]);
    cmulc_sc(R[7], I[7], T.owr[7], T.owi[7]);
#pragma unroll
    for (int b = 0; b < 8; b += 2) {
        u64 br = R[b + 1], bi = I[b + 1];
        R[b + 1] = f2sub(R[b], br);  I[b + 1] = f2sub(I[b], bi);
        R[b] = f2add(R[b], br);      I[b] = f2add(I[b], bi);
    }
    {
        u64 t;
        t = f2neg(I[3]);  I[3] = R[3];  R[3] = t;
        t = f2neg(I[7]);  I[7] = R[7];  R[7] = t;
        u64 br, bi;
        br = R[2];  bi = I[2];
        R[2] = f2sub(R[0], br);  I[2] = f2sub(I[0], bi);
        R[0] = f2add(R[0], br);  I[0] = f2add(I[0], bi);
        br = R[3];  bi = I[3];
        R[3] = f2sub(R[1], br);  I[3] = f2sub(I[1], bi);
        R[1] = f2add(R[1], br);  I[1] = f2add(I[1], bi);
        br = R[6];  bi = I[6];
        R[6] = f2sub(R[4], br);  I[6] = f2sub(I[4], bi);
        R[4] = f2add(R[4], br);  I[4] = f2add(I[4], bi);
        br = R[7];  bi = I[7];
        R[7] = f2sub(R[5], br);  I[7] = f2sub(I[5], bi);
        R[5] = f2add(R[5], br);  I[5] = f2add(I[5], bi);
    }
    {
        u64 nr, ni, t;
        nr = f2mul(f2sub(R[5], I[5]), T.K);
        ni = f2mul(f2add(R[5], I[5]), T.K);
        R[5] = nr;  I[5] = ni;
        t = f2neg(I[6]);  I[6] = R[6];  R[6] = t;
        nr = f2mul(f2neg(f2add(R[7], I[7])), T.K);
        ni = f2mul(f2sub(R[7], I[7]), T.K);
        R[7] = nr;  I[7] = ni;
#pragma unroll
        for (int j = 0; j < 4; j++) {
            u64 br = R[j + 4], bi = I[j + 4];
            R[j + 4] = f2sub(R[j], br);  I[j + 4] = f2sub(I[j], bi);
            R[j] = f2add(R[j], br);      I[j] = f2add(I[j], bi);
        }
    }
}

__device__ __forceinline__ void applyH(u64 (&R)[8], u64 (&I)[8],
                                       const float (&Hr)[8], const float (&Hi)[8])
{
#pragma unroll
    for (int j = 0; j < 8; j++)
        cmul_sc(R[j], I[j], Hr[j], Hi[j]);
}

__device__ __forceinline__ void transmit(u64 (&R)[8], u64 (&I)[8],
                                         const float2* __restrict__ tA,
                                         const float2* __restrict__ tB, int l16)
{
#pragma unroll
    for (int j = 0; j < 8; j++) {
        const int e = l16 + 16 * j;
        float2 a = tA[e], b = tB[e];
        u64 Tr = pk(a.x, b.x), Ti = pk(a.y, b.y);
        u64 rr = f2sub(f2mul(R[j], Tr), f2mul(I[j], Ti));
        I[j] = f2fma(R[j], Ti, f2mul(I[j], Tr));
        R[j] = rr;
    }
}

// -------------------- precompute T = exp(iV), both orientations -------------
__global__ void msp_maketrans(const float* __restrict__ V)
{
    __shared__ float2 tile[32][33];
    const int z  = blockIdx.z;
    const int by = blockIdx.y * 32, bx = blockIdx.x * 32;
    const int tx = threadIdx.x, ty = threadIdx.y;
#pragma unroll
    for (int dy = ty; dy < 32; dy += 8) {
        const int y = by + dy, x = bx + tx;
        float v = V[(z * 512 + y) * 512 + x];
        float s, c;
        __sincosf(v, &s, &c);
        float2 t = make_float2(c, s);
        g_trow[(z * 512 + y) * 512 + x] = t;
        tile[dy][tx] = t;
    }
    __syncthreads();
#pragma unroll
    for (int dx = ty; dx < 32; dx += 8) {
        const int x = bx + dx, y = by + tx;
        g_tcol[(z * 512 + x) * 512 + y] = tile[tx][dx];
    }
}

// ------------------------------- main kernel --------------------------------
__global__ void __launch_bounds__(512, 1)
msp_main(const float* __restrict__ pre,
         const float* __restrict__ pim,
         const int*   __restrict__ ipos)
{
    extern __shared__ float smem[];
    float* sRe = smem;
    float* sIm = smem + 128 * PITCH;

    const int bid = blockIdx.x;
    const int k   = bid & 255;
    const int m   = bid >> 8;

    int py, px;
    {
        bool i64 = (ipos[1] | ipos[3] | ipos[5] | ipos[7] |
                    ipos[9] | ipos[11] | ipos[13] | ipos[15]) == 0;
        if (i64) { py = ipos[4 * k];  px = ipos[4 * k + 2]; }
        else     { py = ipos[2 * k];  px = ipos[2 * k + 1]; }
    }

    const int tid = threadIdx.x;
    const int l   = tid & 31;
    const int w   = tid >> 5;        // 16 warps
    const int l16 = l & 15;
    const int h   = l >> 4;
    const int baseLine = 2 * (w & 7) + 16 * h + 32 * (w >> 3);

    Tw4 T;
    {
        T.owr[0] = 1.0f;  T.owi[0] = 0.0f;
#pragma unroll
        for (int t = 1; t < 8; t++) {
            float s, c; sincospif((float)(l16 * t) * (1.0f / 64.0f), &s, &c);
            T.owr[t] = c;  T.owi[t] = -s;
        }
        T.K = pk(RSQRT2, RSQRT2);
        { float s, c; sincospif((float)(8 * (l16 & 7)) * (1.0f / 64.0f), &s, &c);
          float tr = (l16 & 8) ? c : 1.0f, ti = (l16 & 8) ? -s : 0.0f;
          T.c8r = pk(tr, tr);  T.c8i = pk(ti, ti); }
        { float s, c; sincospif((float)(16 * (l16 & 3)) * (1.0f / 64.0f), &s, &c);
          float tr = (l16 & 4) ? c : 1.0f, ti = (l16 & 4) ? -s : 0.0f;
          T.c4r = pk(tr, tr);  T.c4i = pk(ti, ti); }
        { float s, c; sincospif((float)(32 * (l16 & 1)) * (1.0f / 64.0f), &s, &c);
          float tr = (l16 & 2) ? c : 1.0f, ti = (l16 & 2) ? -s : 0.0f;
          T.c2r = pk(tr, tr);  T.c2i = pk(ti, ti); }
        float s8 = (l16 & 8) ? -1.0f : 1.0f;  T.sg8 = pk(s8, s8);
        float s4 = (l16 & 4) ? -1.0f : 1.0f;  T.sg4 = pk(s4, s4);
        float s2 = (l16 & 2) ? -1.0f : 1.0f;  T.sg2 = pk(s2, s2);
        float s1 = (l16 & 1) ? -1.0f : 1.0f;  T.sg1 = pk(s1, s1);
    }

    // Fresnel factors at bit-reversed stored positions, 1/128 folded in
    float Hr[8], Hi[8];
#pragma unroll
    for (int j = 0; j < 8; j++) {
        int idx = l16 + 16 * j;
        int fb  = (int)(__brev((unsigned)idx) >> 25);
        float f = (float)(fb < 64 ? fb : fb - 128) * (1.0f / 25.6f);
        float s, c;
        sincospif(-0.25f * f * f, &s, &c);      // lambda*dz = 0.25
        Hr[j] = c * (1.0f / 128.0f);
        Hi[j] = s * (1.0f / 128.0f);
    }

    const float* prm  = pre + m * 16384;
    const float* pimm = pim + m * 16384;

    // Pass schedule (10 passes): even = rows, odd = cols.
    //  0: probe, xT0, conv            5: conv, xT5, conv
    //  1: conv, xT1, conv             6: conv, xT6, conv
    //  2: conv, xT2, conv             7: conv
    //  3: conv, xT3, conv             8: xT7, DIF only
    //  4: conv, xT4, conv             9: DIF only, |.|^2
#pragma unroll 1
    for (int pass = 0; pass < 10; pass++) {
        const bool rows = (pass & 1) == 0;
#pragma unroll 1
        for (int p = 0; p < 2; p++) {
            const int lineA = baseLine + 64 * p, lineB = lineA + 1;
            u64 R[8], I[8];

            // ---- load ----
            if (pass == 0) {
#pragma unroll
                for (int j = 0; j < 8; j++) {
                    const int c = l16 + 16 * j;
                    R[j] = pk(prm[lineA * 128 + c],  prm[lineB * 128 + c]);
                    I[j] = pk(pimm[lineA * 128 + c], pimm[lineB * 128 + c]);
                }
            } else if (rows) {
#pragma unroll
                for (int j = 0; j < 8; j++) {
                    const int c = l16 + 16 * j;
                    R[j] = pk(sRe[lineA * PITCH + c], sRe[lineB * PITCH + c]);
                    I[j] = pk(sIm[lineA * PITCH + c], sIm[lineB * PITCH + c]);
                }
            } else {
#pragma unroll
                for (int j = 0; j < 8; j++) {
                    const int r = l16 + 16 * j;
                    R[j] = pk(sRe[r * PITCH + lineA], sRe[r * PITCH + lineB]);
                    I[j] = pk(sIm[r * PITCH + lineA], sIm[r * PITCH + lineB]);
                }
            }

            // ---- pre-transmit (pass 0: T0; pass 8: T7; both rows) ----
            if (pass == 0 || pass == 8) {
                const int z = (pass == 0) ? 0 : 7;
                const float2* base = g_trow + (z * 512 + py) * 512 + px;
                transmit(R, I, base + lineA * 512, base + lineB * 512, l16);
            }

            dif8(R, I, T);
            if (pass <= 7) {
                applyH(R, I, Hr, Hi);
                dit8(R, I, T);
            }

            // ---- mid-transmit + second conv (passes 1..6) ----
            if (pass >= 1 && pass <= 6) {
                const float2* base = rows
                    ? g_trow + (pass * 512 + py) * 512 + px
                    : g_tcol + (pass * 512 + px) * 512 + py;
                transmit(R, I, base + lineA * 512, base + lineB * 512, l16);
                dif8(R, I, T);
                applyH(R, I, Hr, Hi);
                dit8(R, I, T);
            }

            // ---- store ----
            if (pass == 9) {
#pragma unroll
                for (int j = 0; j < 8; j++) {
                    const int r = l16 + 16 * j;
                    u64 mg = f2fma(R[j], R[j], f2mul(I[j], I[j]));
                    float a, b; upk(mg, a, b);
                    sRe[r * PITCH + lineA] = a;
                    sRe[r * PITCH + lineB] = b;
                }
            } else if (rows) {
#pragma unroll
                for (int j = 0; j < 8; j++) {
                    const int c = l16 + 16 * j;
                    float a, b;
                    upk(R[j], a, b);
                    sRe[lineA * PITCH + c] = a;  sRe[lineB * PITCH + c] = b;
                    upk(I[j], a, b);
                    sIm[lineA * PITCH + c] = a;  sIm[lineB * PITCH + c] = b;
                }
            } else {
#pragma unroll
                for (int j = 0; j < 8; j++) {
                    const int r = l16 + 16 * j;
                    float a, b;
                    upk(R[j], a, b);
                    sRe[r * PITCH + lineA] = a;  sRe[r * PITCH + lineB] = b;
                    upk(I[j], a, b);
                    sIm[r * PITCH + lineA] = a;  sIm[r * PITCH + lineB] = b;
                }
            }
        }
        __syncthreads();
    }

    // bitrev permute |psi|^2 to natural order, vectorized STG.128
    {
        float4* out4 = (float4*)(g_int + ((size_t)bid << 14));
        for (int i = tid; i < 4096; i += 512) {
            const int y = i >> 5;
            const int q = i & 31;
            const int ry = (int)(__brev((unsigned)y) >> 25);
            const int bx = (int)(__brev((unsigned)q) >> 27);
            float4 v;
            v.x = sRe[ry * PITCH + bx];
            v.y = sRe[ry * PITCH + bx + 64];
            v.z = sRe[ry * PITCH + bx + 32];
            v.w = sRe[ry * PITCH + bx + 96];
            out4[i] = v;
        }
    }
}

// ------------------------------ finalize ------------------------------------
__global__ void msp_finalize(float* __restrict__ outp)
{
    const size_t i = ((size_t)blockIdx.x * blockDim.x + threadIdx.x) * 4;
    float4 a = *(const float4*)(g_int + i);
    float4 b = *(const float4*)(g_int + i + ((size_t)1 << 22));
    float4 c = *(const float4*)(g_int + i + ((size_t)2 << 22));
    float4 d = *(const float4*)(g_int + i + ((size_t)3 << 22));
    float4 o;
    o.x = sqrtf(1e-10f + (a.x + b.x + c.x + d.x) * (1.0f / 16384.0f));
    o.y = sqrtf(1e-10f + (a.y + b.y + c.y + d.y) * (1.0f / 16384.0f));
    o.z = sqrtf(1e-10f + (a.z + b.z + c.z + d.z) * (1.0f / 16384.0f));
    o.w = sqrtf(1e-10f + (a.w + b.w + c.w + d.w) * (1.0f / 16384.0f));
    *(float4*)(outp + i) = o;
}

// ------------------------------ launcher ------------------------------------
extern "C" void kernel_launch(void* const* d_in, const int* in_sizes, int n_in,
                              void* d_out, int out_size)
{
    const float* V   = (const float*)d_in[0];
    const float* pre = (const float*)d_in[1];
    const float* pim = (const float*)d_in[2];
    const int*   pos = (const int*)d_in[3];
    float* out = (float*)d_out;
    (void)in_sizes; (void)n_in; (void)out_size;

    msp_maketrans<<<dim3(16, 16, 8), dim3(32, 8)>>>(V);

    const size_t smem = SMEM_FLOATS * sizeof(float);   // 132096 B
    cudaFuncSetAttribute((const void*)msp_main,
                         cudaFuncAttributeMaxDynamicSharedMemorySize,
                         (int)smem);
    msp_main<<<1024, 512, smem>>>(pre, pim, pos);
    msp_finalize<<<4096, 256>>>(out);
}

// round 10
// speedup vs baseline: 1.3848x; 1.0164x over previous
#include <cuda_runtime.h>

// ---------------------------------------------------------------------------
// Multi-slice ptychography, fused, f32x2-packed, 9-pass schedule.
//  0 R: probe, xT0, conv        5 C: conv, xT5, conv
//  1 C: conv, xT1, conv         6 R: conv, xT6, conv
//  2 R: conv, xT2, conv         7 C: conv, xT7, DIF(det-y)
//  3 C: conv, xT3, conv         8 R: DIF(det-x), |.|^2
//  4 R: conv, xT4, conv
// (detector fft2 factors commuted: y-FFT folded into pass 7.)
// SMEM pair-packed: u64[pair][c] = (v[2q][c], v[2q+1][c]) -> rows passes use
// direct LDS.64/STS.64 of packed registers. T=exp(iV) precomputed both ways.
// ---------------------------------------------------------------------------

typedef unsigned long long u64;

#define PITCH2 129                       // u64 units per pair-row
#define SMEM_BYTES (2 * 64 * PITCH2 * 8) // 132096
#define RSQRT2 0.70710678118654752440f

static __device__ float  g_int[4u * 256u * 128u * 128u];    // 64 MB scratch
static __device__ float2 g_trow[8u * 512u * 512u];          // 16 MB T row-major
static __device__ float2 g_tcol[8u * 512u * 512u];          // 16 MB T transposed

// ----------------------------- f32x2 helpers --------------------------------
__device__ __forceinline__ u64 pk(float a, float b) {
    u64 r; asm("mov.b64 %0,{%1,%2};" : "=l"(r) : "f"(a), "f"(b)); return r;
}
__device__ __forceinline__ void upk(u64 v, float& a, float& b) {
    asm("mov.b64 {%0,%1},%2;" : "=f"(a), "=f"(b) : "l"(v));
}
__device__ __forceinline__ u64 f2add(u64 a, u64 b) {
    u64 d; asm("add.rn.f32x2 %0,%1,%2;" : "=l"(d) : "l"(a), "l"(b)); return d;
}
__device__ __forceinline__ u64 f2sub(u64 a, u64 b) {
    u64 d; asm("sub.rn.f32x2 %0,%1,%2;" : "=l"(d) : "l"(a), "l"(b)); return d;
}
__device__ __forceinline__ u64 f2mul(u64 a, u64 b) {
    u64 d; asm("mul.rn.f32x2 %0,%1,%2;" : "=l"(d) : "l"(a), "l"(b)); return d;
}
__device__ __forceinline__ u64 f2fma(u64 a, u64 b, u64 c) {
    u64 d; asm("fma.rn.f32x2 %0,%1,%2,%3;" : "=l"(d) : "l"(a), "l"(b), "l"(c)); return d;
}
__device__ __forceinline__ u64 f2neg(u64 v) {
    return v ^ 0x8000000080000000ull;
}
__device__ __forceinline__ u64 shx(u64 v, int s) {
    float a, b; upk(v, a, b);
    a = __shfl_xor_sync(0xffffffffu, a, s);
    b = __shfl_xor_sync(0xffffffffu, b, s);
    return pk(a, b);
}

__device__ __forceinline__ void cmul_sc(u64& r, u64& i, float tr, float ti) {
    u64 Tr = pk(tr, tr), Ti = pk(ti, ti);
    u64 rr = f2sub(f2mul(r, Tr), f2mul(i, Ti));
    i = f2fma(r, Ti, f2mul(i, Tr));
    r = rr;
}
__device__ __forceinline__ void cmulc_sc(u64& r, u64& i, float tr, float ti) {
    u64 Tr = pk(tr, tr), Ti = pk(ti, ti);
    u64 rr = f2fma(i, Ti, f2mul(r, Tr));
    i = f2sub(f2mul(i, Tr), f2mul(r, Ti));
    r = rr;
}

// ------------------------- twiddle context ----------------------------------
struct Tw4 {
    float owr[8], owi[8];
    u64 K;
    u64 c8r, c8i, c4r, c4i, c2r, c2i;
    u64 sg8, sg4, sg2, sg1;
};

__device__ __forceinline__ void cross_dif(u64 (&R)[8], u64 (&I)[8], int s,
                                          u64 sg, u64 cr, u64 ci)
{
    u64 nci = f2neg(ci);
#pragma unroll
    for (int j = 0; j < 8; j++) {
        u64 pR = shx(R[j], s), pI = shx(I[j], s);
        u64 xR = f2fma(sg, R[j], pR);
        u64 xI = f2fma(sg, I[j], pI);
        R[j] = f2fma(xI, nci, f2mul(xR, cr));
        I[j] = f2fma(xI, cr,  f2mul(xR, ci));
    }
}
__device__ __forceinline__ void cross_dit(u64 (&R)[8], u64 (&I)[8], int s,
                                          u64 sg, u64 cr, u64 ci)
{
    u64 nci = f2neg(ci);
#pragma unroll
    for (int j = 0; j < 8; j++) {
        u64 uR = f2fma(I[j], ci,  f2mul(R[j], cr));
        u64 uI = f2fma(R[j], nci, f2mul(I[j], cr));
        u64 pR = shx(uR, s), pI = shx(uI, s);
        R[j] = f2fma(sg, uR, pR);
        I[j] = f2fma(sg, uI, pI);
    }
}

__device__ __forceinline__ void dif8(u64 (&R)[8], u64 (&I)[8], const Tw4& T)
{
    {
        u64 dr, di;
        dr = f2sub(R[0], R[4]);  di = f2sub(I[0], I[4]);
        R[0] = f2add(R[0], R[4]);  I[0] = f2add(I[0], I[4]);
        R[4] = dr;  I[4] = di;
        dr = f2sub(R[1], R[5]);  di = f2sub(I[1], I[5]);
        R[1] = f2add(R[1], R[5]);  I[1] = f2add(I[1], I[5]);
        R[5] = f2mul(f2add(dr, di), T.K);
        I[5] = f2mul(f2sub(di, dr), T.K);
        dr = f2sub(R[2], R[6]);  di = f2sub(I[2], I[6]);
        R[2] = f2add(R[2], R[6]);  I[2] = f2add(I[2], I[6]);
        R[6] = di;  I[6] = f2neg(dr);
        dr = f2sub(R[3], R[7]);  di = f2sub(I[3], I[7]);
        R[3] = f2add(R[3], R[7]);  I[3] = f2add(I[3], I[7]);
        R[7] = f2mul(f2sub(di, dr), T.K);
        I[7] = f2mul(f2neg(f2add(dr, di)), T.K);
    }
    {
        u64 dr, di;
        dr = f2sub(R[0], R[2]);  di = f2sub(I[0], I[2]);
        R[0] = f2add(R[0], R[2]);  I[0] = f2add(I[0], I[2]);
        R[2] = dr;  I[2] = di;
        dr = f2sub(R[4], R[6]);  di = f2sub(I[4], I[6]);
        R[4] = f2add(R[4], R[6]);  I[4] = f2add(I[4], I[6]);
        R[6] = dr;  I[6] = di;
        dr = f2sub(R[1], R[3]);  di = f2sub(I[1], I[3]);
        R[1] = f2add(R[1], R[3]);  I[1] = f2add(I[1], I[3]);
        R[3] = di;  I[3] = f2neg(dr);
        dr = f2sub(R[5], R[7]);  di = f2sub(I[5], I[7]);
        R[5] = f2add(R[5], R[7]);  I[5] = f2add(I[5], I[7]);
        R[7] = di;  I[7] = f2neg(dr);
    }
#pragma unroll
    for (int b = 0; b < 8; b += 2) {
        u64 dr = f2sub(R[b], R[b + 1]), di = f2sub(I[b], I[b + 1]);
        R[b] = f2add(R[b], R[b + 1]);  I[b] = f2add(I[b], I[b + 1]);
        R[b + 1] = dr;  I[b + 1] = di;
    }
    cmul_sc(R[1], I[1], T.owr[4], T.owi[4]);
    cmul_sc(R[2], I[2], T.owr[2], T.owi[2]);
    cmul_sc(R[3], I[3], T.owr[6], T.owi[6]);
    cmul_sc(R[4], I[4], T.owr[1], T.owi[1]);
    cmul_sc(R[5], I[5], T.owr[5], T.owi[5]);
    cmul_sc(R[6], I[6], T.owr[3], T.owi[3]);
    cmul_sc(R[7], I[7], T.owr[7], T.owi[7]);
    cross_dif(R, I, 8, T.sg8, T.c8r, T.c8i);
    cross_dif(R, I, 4, T.sg4, T.c4r, T.c4i);
    cross_dif(R, I, 2, T.sg2, T.c2r, T.c2i);
#pragma unroll
    for (int j = 0; j < 8; j++) {
        u64 pR = shx(R[j], 1), pI = shx(I[j], 1);
        R[j] = f2fma(T.sg1, R[j], pR);
        I[j] = f2fma(T.sg1, I[j], pI);
    }
}

__device__ __forceinline__ void dit8(u64 (&R)[8], u64 (&I)[8], const Tw4& T)
{
#pragma unroll
    for (int j = 0; j < 8; j++) {
        u64 pR = shx(R[j], 1), pI = shx(I[j], 1);
        R[j] = f2fma(T.sg1, R[j], pR);
        I[j] = f2fma(T.sg1, I[j], pI);
    }
    cross_dit(R, I, 2, T.sg2, T.c2r, T.c2i);
    cross_dit(R, I, 4, T.sg4, T.c4r, T.c4i);
    cross_dit(R, I, 8, T.sg8, T.c8r, T.c8i);
    cmulc_sc(R[1], I[1], T.owr[4], T.owi[4]);
    cmulc_sc(R[2], I[2], T.owr[2], T.owi[2]);
    cmulc_sc(R[3], I[3], T.owr[6], T.owi[6]);
    cmulc_sc(R[4], I[4], T.owr[1], T.owi[1]);
    cmulc_sc(R[5], I[5], T.owr[5], T.owi[5]);
    cmulc_sc(R[6], I[6], T.owr[3], T.owi[3]);
    cmulc_sc(R[7], I[7], T.owr[7], T.owi[7]);
#pragma unroll
    for (int b = 0; b < 8; b += 2) {
        u64 br = R[b + 1], bi = I[b + 1];
        R[b + 1] = f2sub(R[b], br);  I[b + 1] = f2sub(I[b], bi);
        R[b] = f2add(R[b], br);      I[b] = f2add(I[b], bi);
    }
    {
        u64 t;
        t = f2neg(I[3]);  I[3] = R[3];  R[3] = t;
        t = f2neg(I[7]);  I[7] = R[7];  R[7] = t;
        u64 br, bi;
        br = R[2];  bi = I[2];
        R[2] = f2sub(R[0], br);  I[2] = f2sub(I[0], bi);
        R[0] = f2add(R[0], br);  I[0] = f2add(I[0], bi);
        br = R[3];  bi = I[3];
        R[3] = f2sub(R[1], br);  I[3] = f2sub(I[1], bi);
        R[1] = f2add(R[1], br);  I[1] = f2add(I[1], bi);
        br = R[6];  bi = I[6];
        R[6] = f2sub(R[4], br);  I[6] = f2sub(I[4], bi);
        R[4] = f2add(R[4], br);  I[4] = f2add(I[4], bi);
        br = R[7];  bi = I[7];
        R[7] = f2sub(R[5], br);  I[7] = f2sub(I[5], bi);
        R[5] = f2add(R[5], br);  I[5] = f2add(I[5], bi);
    }
    {
        u64 nr, ni, t;
        nr = f2mul(f2sub(R[5], I[5]), T.K);
        ni = f2mul(f2add(R[5], I[5]), T.K);
        R[5] = nr;  I[5] = ni;
        t = f2neg(I[6]);  I[6] = R[6];  R[6] = t;
        nr = f2mul(f2neg(f2add(R[7], I[7])), T.K);
        ni = f2mul(f2sub(R[7], I[7]), T.K);
        R[7] = nr;  I[7] = ni;
#pragma unroll
        for (int j = 0; j < 4; j++) {
            u64 br = R[j + 4], bi = I[j + 4];
            R[j + 4] = f2sub(R[j], br);  I[j + 4] = f2sub(I[j], bi);
            R[j] = f2add(R[j], br);      I[j] = f2add(I[j], bi);
        }
    }
}

__device__ __forceinline__ void applyH(u64 (&R)[8], u64 (&I)[8],
                                       const float (&Hr)[8], const float (&Hi)[8])
{
#pragma unroll
    for (int j = 0; j < 8; j++)
        cmul_sc(R[j], I[j], Hr[j], Hi[j]);
}

__device__ __forceinline__ void transmit(u64 (&R)[8], u64 (&I)[8],
                                         const float2* __restrict__ tA,
                                         const float2* __restrict__ tB, int l16)
{
#pragma unroll
    for (int j = 0; j < 8; j++) {
        const int e = l16 + 16 * j;
        float2 a = tA[e], b = tB[e];
        u64 Tr = pk(a.x, b.x), Ti = pk(a.y, b.y);
        u64 rr = f2sub(f2mul(R[j], Tr), f2mul(I[j], Ti));
        I[j] = f2fma(R[j], Ti, f2mul(I[j], Tr));
        R[j] = rr;
    }
}

// -------------------- precompute T = exp(iV), both orientations -------------
__global__ void msp_maketrans(const float* __restrict__ V)
{
    __shared__ float2 tile[32][33];
    const int z  = blockIdx.z;
    const int by = blockIdx.y * 32, bx = blockIdx.x * 32;
    const int tx = threadIdx.x, ty = threadIdx.y;
#pragma unroll
    for (int dy = ty; dy < 32; dy += 8) {
        const int y = by + dy, x = bx + tx;
        float v = V[(z * 512 + y) * 512 + x];
        float s, c;
        __sincosf(v, &s, &c);
        float2 t = make_float2(c, s);
        g_trow[(z * 512 + y) * 512 + x] = t;
        tile[dy][tx] = t;
    }
    __syncthreads();
#pragma unroll
    for (int dx = ty; dx < 32; dx += 8) {
        const int x = bx + dx, y = by + tx;
        g_tcol[(z * 512 + x) * 512 + y] = tile[tx][dx];
    }
}

// ------------------------------- main kernel --------------------------------
__global__ void __launch_bounds__(512, 1)
msp_main(const float* __restrict__ pre,
         const float* __restrict__ pim,
         const int*   __restrict__ ipos)
{
    extern __shared__ u64 smem[];
    u64* sR2 = smem;                 // pair-packed Re: [pair q][c]
    u64* sI2 = smem + 64 * PITCH2;   // pair-packed Im

    const int bid = blockIdx.x;
    const int k   = bid & 255;
    const int m   = bid >> 8;

    int py, px;
    {
        bool i64 = (ipos[1] | ipos[3] | ipos[5] | ipos[7] |
                    ipos[9] | ipos[11] | ipos[13] | ipos[15]) == 0;
        if (i64) { py = ipos[4 * k];  px = ipos[4 * k + 2]; }
        else     { py = ipos[2 * k];  px = ipos[2 * k + 1]; }
    }

    const int tid = threadIdx.x;
    const int l   = tid & 31;
    const int w   = tid >> 5;        // 16 warps
    const int l16 = l & 15;
    const int h   = l >> 4;
    // half-warps' lines differ by 8 -> packed banks stay conflict-free
    const int baseLine = 2 * (w & 3) + 8 * h + 16 * ((w >> 2) & 1) + 32 * (w >> 3);

    Tw4 T;
    {
        T.owr[0] = 1.0f;  T.owi[0] = 0.0f;
#pragma unroll
        for (int t = 1; t < 8; t++) {
            float s, c; sincospif((float)(l16 * t) * (1.0f / 64.0f), &s, &c);
            T.owr[t] = c;  T.owi[t] = -s;
        }
        T.K = pk(RSQRT2, RSQRT2);
        { float s, c; sincospif((float)(8 * (l16 & 7)) * (1.0f / 64.0f), &s, &c);
          float tr = (l16 & 8) ? c : 1.0f, ti = (l16 & 8) ? -s : 0.0f;
          T.c8r = pk(tr, tr);  T.c8i = pk(ti, ti); }
        { float s, c; sincospif((float)(16 * (l16 & 3)) * (1.0f / 64.0f), &s, &c);
          float tr = (l16 & 4) ? c : 1.0f, ti = (l16 & 4) ? -s : 0.0f;
          T.c4r = pk(tr, tr);  T.c4i = pk(ti, ti); }
        { float s, c; sincospif((float)(32 * (l16 & 1)) * (1.0f / 64.0f), &s, &c);
          float tr = (l16 & 2) ? c : 1.0f, ti = (l16 & 2) ? -s : 0.0f;
          T.c2r = pk(tr, tr);  T.c2i = pk(ti, ti); }
        float s8 = (l16 & 8) ? -1.0f : 1.0f;  T.sg8 = pk(s8, s8);
        float s4 = (l16 & 4) ? -1.0f : 1.0f;  T.sg4 = pk(s4, s4);
        float s2 = (l16 & 2) ? -1.0f : 1.0f;  T.sg2 = pk(s2, s2);
        float s1 = (l16 & 1) ? -1.0f : 1.0f;  T.sg1 = pk(s1, s1);
    }

    // Fresnel factors at bit-reversed stored positions, 1/128 folded in
    float Hr[8], Hi[8];
#pragma unroll
    for (int j = 0; j < 8; j++) {
        int idx = l16 + 16 * j;
        int fb  = (int)(__brev((unsigned)idx) >> 25);
        float f = (float)(fb < 64 ? fb : fb - 128) * (1.0f / 25.6f);
        float s, c;
        sincospif(-0.25f * f * f, &s, &c);      // lambda*dz = 0.25
        Hr[j] = c * (1.0f / 128.0f);
        Hi[j] = s * (1.0f / 128.0f);
    }

    const float* prm  = pre + m * 16384;
    const float* pimm = pim + m * 16384;

#pragma unroll 1
    for (int pass = 0; pass < 9; pass++) {
        const bool rows = (pass & 1) == 0;
#pragma unroll 1
        for (int p = 0; p < 2; p++) {
            const int lineA = baseLine + 64 * p, lineB = lineA + 1;
            const int q = lineA >> 1;               // pair index (rows passes)
            u64 R[8], I[8];

            // ---- load ----
            if (pass == 0) {
#pragma unroll
                for (int j = 0; j < 8; j++) {
                    const int c = l16 + 16 * j;
                    R[j] = pk(prm[lineA * 128 + c],  prm[lineB * 128 + c]);
                    I[j] = pk(pimm[lineA * 128 + c], pimm[lineB * 128 + c]);
                }
            } else if (rows) {
#pragma unroll
                for (int j = 0; j < 8; j++) {
                    const int c = l16 + 16 * j;
                    R[j] = sR2[q * PITCH2 + c];
                    I[j] = sI2[q * PITCH2 + c];
                }
            } else {
                const int rb = l16 & 1;
#pragma unroll
                for (int j = 0; j < 8; j++) {
                    const int rq = (l16 >> 1) + 8 * j;
                    const float* fr = (const float*)(sR2 + rq * PITCH2 + lineA);
                    const float* fi = (const float*)(sI2 + rq * PITCH2 + lineA);
                    R[j] = pk(fr[rb], fr[rb + 2]);
                    I[j] = pk(fi[rb], fi[rb + 2]);
                }
            }

            // ---- pre-transmit (pass 0 only) ----
            if (pass == 0) {
                const float2* base = g_trow + py * 512 + px;
                transmit(R, I, base + lineA * 512, base + lineB * 512, l16);
            }

            dif8(R, I, T);
            if (pass <= 7) {
                applyH(R, I, Hr, Hi);
                dit8(R, I, T);
            }

            // ---- mid-transmit + second FFT block ----
            if (pass >= 1 && pass <= 7) {
                const float2* base = rows
                    ? g_trow + (pass * 512 + py) * 512 + px
                    : g_tcol + (pass * 512 + px) * 512 + py;
                transmit(R, I, base + lineA * 512, base + lineB * 512, l16);
                dif8(R, I, T);
                if (pass <= 6) {            // pass 7: detector y-FFT, no H/dit
                    applyH(R, I, Hr, Hi);
                    dit8(R, I, T);
                }
            }

            // ---- store ----
            if (pass == 8) {
                // detector intensity, pair-packed direct STS.64
#pragma unroll
                for (int j = 0; j < 8; j++) {
                    const int c = l16 + 16 * j;
                    sR2[q * PITCH2 + c] = f2fma(R[j], R[j], f2mul(I[j], I[j]));
                }
            } else if (rows) {
#pragma unroll
                for (int j = 0; j < 8; j++) {
                    const int c = l16 + 16 * j;
                    sR2[q * PITCH2 + c] = R[j];
                    sI2[q * PITCH2 + c] = I[j];
                }
            } else {
                const int rb = l16 & 1;
#pragma unroll
                for (int j = 0; j < 8; j++) {
                    const int rq = (l16 >> 1) + 8 * j;
                    float* fr = (float*)(sR2 + rq * PITCH2 + lineA);
                    float* fi = (float*)(sI2 + rq * PITCH2 + lineA);
                    float a, b;
                    upk(R[j], a, b);  fr[rb] = a;  fr[rb + 2] = b;
                    upk(I[j], a, b);  fi[rb] = a;  fi[rb + 2] = b;
                }
            }
        }
        __syncthreads();
    }

    // bitrev permute |psi|^2 to natural order, vectorized STG.128
    // mag storage: float = component (ry&1) of sR2[(ry>>1)*PITCH2 + rx]
    {
        float4* out4 = (float4*)(g_int + ((size_t)bid << 14));
        for (int i = tid; i < 4096; i += 512) {
            const int y = i >> 5;
            const int qx = i & 31;
            const int ry = (int)(__brev((unsigned)y) >> 25);
            const int bx = (int)(__brev((unsigned)qx) >> 27);
            const float* row = (const float*)(sR2 + (ry >> 1) * PITCH2);
            const int cc = ry & 1;
            float4 v;
            v.x = row[2 * bx + cc];
            v.y = row[2 * (bx + 64) + cc];
            v.z = row[2 * (bx + 32) + cc];
            v.w = row[2 * (bx + 96) + cc];
            out4[i] = v;
        }
    }
}

// ------------------------------ finalize ------------------------------------
__global__ void msp_finalize(float* __restrict__ outp)
{
    const size_t i = ((size_t)blockIdx.x * blockDim.x + threadIdx.x) * 4;
    float4 a = *(const float4*)(g_int + i);
    float4 b = *(const float4*)(g_int + i + ((size_t)1 << 22));
    float4 c = *(const float4*)(g_int + i + ((size_t)2 << 22));
    float4 d = *(const float4*)(g_int + i + ((size_t)3 << 22));
    float4 o;
    o.x = sqrtf(1e-10f + (a.x + b.x + c.x + d.x) * (1.0f / 16384.0f));
    o.y = sqrtf(1e-10f + (a.y + b.y + c.y + d.y) * (1.0f / 16384.0f));
    o.z = sqrtf(1e-10f + (a.z + b.z + c.z + d.z) * (1.0f / 16384.0f));
    o.w = sqrtf(1e-10f + (a.w + b.w + c.w + d.w) * (1.0f / 16384.0f));
    *(float4*)(outp + i) = o;
}

// ------------------------------ launcher ------------------------------------
extern "C" void kernel_launch(void* const* d_in, const int* in_sizes, int n_in,
                              void* d_out, int out_size)
{
    const float* V   = (const float*)d_in[0];
    const float* pre = (const float*)d_in[1];
    const float* pim = (const float*)d_in[2];
    const int*   pos = (const int*)d_in[3];
    float* out = (float*)d_out;
    (void)in_sizes; (void)n_in; (void)out_size;

    msp_maketrans<<<dim3(16, 16, 8), dim3(32, 8)>>>(V);

    cudaFuncSetAttribute((const void*)msp_main,
                         cudaFuncAttributeMaxDynamicSharedMemorySize,
                         SMEM_BYTES);
    msp_main<<<1024, 512, SMEM_BYTES>>>(pre, pim, pos);
    msp_finalize<<<4096, 256>>>(out);
}